// round 1
// baseline (speedup 1.0000x reference)
#include <cuda_runtime.h>

#define Bb 4
#define Tt 2048
#define Cc 1024
#define Hh 16
#define Dd 64
#define NQKV 3072
#define Mrows 8192

// scratch (allocation-free: __device__ globals)
__device__ float g_q[Bb*Hh*Tt*Dd];
__device__ float g_k[Bb*Hh*Tt*Dd];
__device__ float g_v[Bb*Hh*Tt*Dd];
__device__ float g_y[(size_t)Bb*Tt*Cc];

// ---------------------------------------------------------------------------
// SGEMM: out = A[M,1024] @ W[1024,NTOT] + bias
// MODE 0: A = x, scatter result into g_q/g_k/g_v as [B,H,T,D]
// MODE 1: A = g_y, write out[M, NTOT] (final projection)
// Tile 128x128, BK=16, 256 threads, 8x8 per thread (strided i*16 mapping).
// ---------------------------------------------------------------------------
template<int NTOT, int MODE>
__global__ __launch_bounds__(256)
void sgemm_kernel(const float* __restrict__ Aarg,
                  const float* __restrict__ W,
                  const float* __restrict__ bias,
                  float* __restrict__ out)
{
    const int K = 1024;
    __shared__ float As[16][128];
    __shared__ float Bs[16][128];

    const float* A = (MODE == 0) ? Aarg : (const float*)g_y;

    const int tid = threadIdx.x;
    const int tx = tid & 15;
    const int ty = tid >> 4;
    const int row0 = blockIdx.y * 128;
    const int col0 = blockIdx.x * 128;

    float acc[8][8];
    #pragma unroll
    for (int i = 0; i < 8; i++)
        #pragma unroll
        for (int j = 0; j < 8; j++) acc[i][j] = 0.f;

    for (int kt = 0; kt < K; kt += 16) {
        // A tile: 128 rows x 16 cols (store transposed As[k][row])
        #pragma unroll
        for (int i = 0; i < 2; i++) {
            int s  = tid * 2 + i;      // 0..511 float4 slots
            int r  = s >> 2;           // row in tile
            int c4 = s & 3;            // which float4 of the 16 k-cols
            float4 a = *(const float4*)(A + (size_t)(row0 + r) * K + kt + c4 * 4);
            As[c4*4+0][r] = a.x;
            As[c4*4+1][r] = a.y;
            As[c4*4+2][r] = a.z;
            As[c4*4+3][r] = a.w;
        }
        // B tile: 16 rows x 128 cols
        #pragma unroll
        for (int i = 0; i < 2; i++) {
            int s  = tid * 2 + i;
            int kr = s >> 5;
            int c4 = s & 31;
            float4 b = *(const float4*)(W + (size_t)(kt + kr) * NTOT + col0 + c4 * 4);
            *(float4*)(&Bs[kr][c4 * 4]) = b;
        }
        __syncthreads();

        #pragma unroll
        for (int k = 0; k < 16; k++) {
            float a[8], b[8];
            #pragma unroll
            for (int i = 0; i < 8; i++) a[i] = As[k][ty + i * 16];
            #pragma unroll
            for (int j = 0; j < 8; j++) b[j] = Bs[k][tx + j * 16];
            #pragma unroll
            for (int i = 0; i < 8; i++)
                #pragma unroll
                for (int j = 0; j < 8; j++)
                    acc[i][j] += a[i] * b[j];
        }
        __syncthreads();
    }

    #pragma unroll
    for (int i = 0; i < 8; i++) {
        const int m = row0 + ty + i * 16;
        #pragma unroll
        for (int j = 0; j < 8; j++) {
            const int n = col0 + tx + j * 16;
            float v = acc[i][j] + bias[n];
            if (MODE == 0) {
                // scatter into [B,H,T,D]
                int b_   = m >> 11;        // m / T
                int t    = m & 2047;       // m % T
                int which = n >> 10;       // n / C : 0=q 1=k 2=v
                int cc   = n & 1023;
                int h    = cc >> 6;
                int d    = cc & 63;
                float* dst = (which == 0) ? g_q : (which == 1) ? g_k : g_v;
                dst[(((size_t)b_ * Hh + h) * Tt + t) * Dd + d] = v;
            } else {
                out[(size_t)m * NTOT + n] = v;
            }
        }
    }
}

// ---------------------------------------------------------------------------
// Flash attention (fp32): grid (T/128, B*H), 128 threads, 1 query row/thread.
// Online softmax in chunks of 16 keys; K/V staged 64 keys at a time in SMEM.
// ---------------------------------------------------------------------------
__global__ __launch_bounds__(128, 2)
void attn_kernel()
{
    __shared__ float4 Ks[64][16];   // 64 keys x 64 floats
    __shared__ float4 Vs[64][16];

    const int tid = threadIdx.x;
    const int qi  = blockIdx.x * 128 + tid;
    const int bh  = blockIdx.y;

    const float* __restrict__ qptr  = g_q + ((size_t)bh * Tt + qi) * Dd;
    const float* __restrict__ kbase = g_k + (size_t)bh * Tt * Dd;
    const float* __restrict__ vbase = g_v + (size_t)bh * Tt * Dd;

    float q[64];
    #pragma unroll
    for (int d = 0; d < 64; d++) q[d] = qptr[d] * 0.125f;  // 1/sqrt(64)

    float o[64];
    #pragma unroll
    for (int d = 0; d < 64; d++) o[d] = 0.f;
    float mval = -1e30f;
    float lsum = 0.f;

    for (int kt = 0; kt < Tt; kt += 64) {
        __syncthreads();
        #pragma unroll
        for (int i = 0; i < 8; i++) {
            int s = tid + 128 * i;           // 0..1023
            int r = s >> 4;
            int c = s & 15;
            Ks[r][c] = ((const float4*)(kbase + (size_t)(kt + r) * Dd))[c];
            Vs[r][c] = ((const float4*)(vbase + (size_t)(kt + r) * Dd))[c];
        }
        __syncthreads();

        #pragma unroll 1
        for (int cch = 0; cch < 4; cch++) {
            float s_[16];
            #pragma unroll
            for (int j = 0; j < 16; j++) {
                float acc0 = 0.f, acc1 = 0.f;   // 2 chains to hide FFMA latency
                #pragma unroll
                for (int d4 = 0; d4 < 16; d4++) {
                    float4 kk = Ks[cch * 16 + j][d4];
                    acc0 += q[d4*4+0] * kk.x;
                    acc1 += q[d4*4+1] * kk.y;
                    acc0 += q[d4*4+2] * kk.z;
                    acc1 += q[d4*4+3] * kk.w;
                }
                s_[j] = acc0 + acc1;
            }
            float mt = mval;
            #pragma unroll
            for (int j = 0; j < 16; j++) mt = fmaxf(mt, s_[j]);
            float fac = __expf(mval - mt);
            mval = mt;
            lsum *= fac;
            #pragma unroll
            for (int d = 0; d < 64; d++) o[d] *= fac;
            #pragma unroll
            for (int j = 0; j < 16; j++) {
                float p = __expf(s_[j] - mval);
                lsum += p;
                #pragma unroll
                for (int d4 = 0; d4 < 16; d4++) {
                    float4 vv = Vs[cch * 16 + j][d4];
                    o[d4*4+0] += p * vv.x;
                    o[d4*4+1] += p * vv.y;
                    o[d4*4+2] += p * vv.z;
                    o[d4*4+3] += p * vv.w;
                }
            }
        }
    }

    // write y [B,T,C]
    const int b_ = bh >> 4;
    const int h  = bh & 15;
    const float inv = 1.f / lsum;
    float* yp = g_y + ((size_t)b_ * Tt + qi) * Cc + h * 64;
    #pragma unroll
    for (int d = 0; d < 64; d++) yp[d] = o[d] * inv;
}

// ---------------------------------------------------------------------------
extern "C" void kernel_launch(void* const* d_in, const int* in_sizes, int n_in,
                              void* d_out, int out_size)
{
    const float* x      = (const float*)d_in[0];
    const float* W_attn = (const float*)d_in[1];
    const float* b_attn = (const float*)d_in[2];
    const float* W_proj = (const float*)d_in[3];
    const float* b_proj = (const float*)d_in[4];
    float* out = (float*)d_out;

    // 1) QKV projection + head scatter
    sgemm_kernel<NQKV, 0><<<dim3(NQKV / 128, Mrows / 128), 256>>>(x, W_attn, b_attn, nullptr);
    // 2) attention
    attn_kernel<<<dim3(Tt / 128, Bb * Hh), 128>>>();
    // 3) output projection
    sgemm_kernel<Cc, 1><<<dim3(Cc / 128, Mrows / 128), 256>>>(nullptr, W_proj, b_proj, out);
}

// round 3
// speedup vs baseline: 1.4385x; 1.4385x over previous
#include <cuda_runtime.h>
#include <cuda_bf16.h>
#include <cstdint>

#define Bb 4
#define Tt 2048
#define Cc 1024
#define Hh 16
#define Dd 64
#define Kdim 1024
#define NQKV 3072
#define Mrows 8192

// ---------------------------------------------------------------------------
// scratch (__device__ globals; allocation-free)
// ---------------------------------------------------------------------------
__device__ float g_q[Bb*Hh*Tt*Dd];
__device__ float g_k[Bb*Hh*Tt*Dd];
__device__ float g_v[Bb*Hh*Tt*Dd];
__device__ float g_y[(size_t)Bb*Tt*Cc];

__device__ uint16_t g_xhi[(size_t)Mrows*Kdim];
__device__ uint16_t g_xlo[(size_t)Mrows*Kdim];
__device__ uint16_t g_yhi[(size_t)Mrows*Kdim];
__device__ uint16_t g_ylo[(size_t)Mrows*Kdim];
__device__ uint16_t g_wta_hi[(size_t)NQKV*Kdim];   // W_attn^T  [3072,1024]
__device__ uint16_t g_wta_lo[(size_t)NQKV*Kdim];
__device__ uint16_t g_wtp_hi[(size_t)Cc*Kdim];     // W_proj^T  [1024,1024]
__device__ uint16_t g_wtp_lo[(size_t)Cc*Kdim];

// ---------------------------------------------------------------------------
// helpers
// ---------------------------------------------------------------------------
__device__ __forceinline__ uint32_t smem_u32(const void* p) {
    uint32_t a;
    asm("{ .reg .u64 t; cvta.to.shared.u64 t, %1; cvt.u32.u64 %0, t; }" : "=r"(a) : "l"(p));
    return a;
}
__device__ __forceinline__ void cp16(uint32_t dst, const void* src) {
    asm volatile("cp.async.cg.shared.global [%0], [%1], 16;" :: "r"(dst), "l"(src));
}
#define CP_COMMIT() asm volatile("cp.async.commit_group;" ::: "memory")
#define CP_WAIT(n)  asm volatile("cp.async.wait_group %0;" :: "n"(n) : "memory")

__device__ __forceinline__ void mma16816(float d[4], const uint32_t a[4], const uint32_t b[2]) {
    asm volatile(
        "mma.sync.aligned.m16n8k16.row.col.f32.bf16.bf16.f32 "
        "{%0,%1,%2,%3}, {%4,%5,%6,%7}, {%8,%9}, {%0,%1,%2,%3};"
        : "+f"(d[0]), "+f"(d[1]), "+f"(d[2]), "+f"(d[3])
        : "r"(a[0]), "r"(a[1]), "r"(a[2]), "r"(a[3]), "r"(b[0]), "r"(b[1]));
}

// ---------------------------------------------------------------------------
// prep kernels: fp32 -> (bf16_hi, bf16_lo)
// ---------------------------------------------------------------------------
__device__ __forceinline__ void split_one(float v, uint16_t& h, uint16_t& l) {
    __nv_bfloat16 hb = __float2bfloat16(v);
    float rem = v - __bfloat162float(hb);
    __nv_bfloat16 lb = __float2bfloat16(rem);
    h = *reinterpret_cast<uint16_t*>(&hb);
    l = *reinterpret_cast<uint16_t*>(&lb);
}

// src==nullptr -> split g_y into g_yhi/g_ylo; else split x into g_xhi/g_xlo
__global__ void split_kernel(const float* __restrict__ src) {
    const float* s = src ? src : (const float*)g_y;
    uint16_t* hi = src ? g_xhi : g_yhi;
    uint16_t* lo = src ? g_xlo : g_ylo;
    size_t n = (size_t)Mrows * Kdim;
    for (size_t i = blockIdx.x * (size_t)blockDim.x + threadIdx.x; i < n;
         i += (size_t)gridDim.x * blockDim.x)
        split_one(s[i], hi[i], lo[i]);
}

// transpose+split: W[Kdim][N] -> Wt[N][Kdim] (hi/lo). WHICH: 0 = attn, 1 = proj
template<int WHICH, int N>
__global__ void transpose_split_kernel(const float* __restrict__ W) {
    uint16_t* hi = (WHICH == 0) ? g_wta_hi : g_wtp_hi;
    uint16_t* lo = (WHICH == 0) ? g_wta_lo : g_wtp_lo;
    __shared__ float t[32][33];
    int n0 = blockIdx.x * 32, k0 = blockIdx.y * 32;
    #pragma unroll
    for (int i = 0; i < 4; i++)
        t[threadIdx.y + 8 * i][threadIdx.x] = W[(size_t)(k0 + threadIdx.y + 8 * i) * N + n0 + threadIdx.x];
    __syncthreads();
    #pragma unroll
    for (int i = 0; i < 4; i++) {
        int n = n0 + threadIdx.y + 8 * i;
        int k = k0 + threadIdx.x;
        uint16_t h, l;
        split_one(t[threadIdx.x][threadIdx.y + 8 * i], h, l);
        hi[(size_t)n * Kdim + k] = h;
        lo[(size_t)n * Kdim + k] = l;
    }
}

// ---------------------------------------------------------------------------
// mma.sync GEMM: D[M,N] = A[M,K] @ Wt[N,K]^T + bias   (3-pass bf16 split)
// Block 128x128, BK=32, 8 warps (4 M x 2 N), warp tile 32x64.
// SMEM rows padded to 40 bf16 (80B): fragment LDS.32 banks (g*20+t)%32 are a
// permutation over g=0..7,t=0..3 -> conflict-free.
// MODE 0: A = x(split), B = W_attn^T, scatter into g_q/g_k/g_v
// MODE 1: A = g_y(split), B = W_proj^T, write out
// ---------------------------------------------------------------------------
#define BK 32
#define NSTG (Kdim / BK)           // 32
#define ROWB 80                    // padded row bytes (40 bf16)
#define MAT_B (128 * ROWB)         // 10240 bytes per matrix tile
#define STAGE_B (4 * MAT_B)        // Ah, Al, Bh, Bl = 40960
#define GEMM_SMEM (2 * STAGE_B)    // 81920

__device__ __forceinline__ void preload_stage(uint32_t st,
        const uint16_t* __restrict__ Ahi, const uint16_t* __restrict__ Alo,
        const uint16_t* __restrict__ Bhi, const uint16_t* __restrict__ Blo,
        int row0, int col0, int kc, int tid)
{
    #pragma unroll
    for (int i = 0; i < 2; i++) {
        int idx = tid + i * 256;          // 0..511
        int r = idx >> 2;                 // tile row 0..127
        int c = idx & 3;                  // 8-elem chunk 0..3
        uint32_t off = (uint32_t)(r * ROWB + c * 16);
        size_t gA = (size_t)(row0 + r) * Kdim + kc + c * 8;
        size_t gB = (size_t)(col0 + r) * Kdim + kc + c * 8;
        cp16(st + 0 * MAT_B + off, Ahi + gA);
        cp16(st + 1 * MAT_B + off, Alo + gA);
        cp16(st + 2 * MAT_B + off, Bhi + gB);
        cp16(st + 3 * MAT_B + off, Blo + gB);
    }
}

template<int MODE>
__global__ void __launch_bounds__(256) mma_gemm_kernel(const float* __restrict__ bias,
                                                       float* __restrict__ out)
{
    extern __shared__ char smem[];
    const uint32_t sb = smem_u32(smem);
    const int tid  = threadIdx.x;
    const int wid  = tid >> 5;
    const int lane = tid & 31;
    const int g = lane >> 2;       // group 0..7
    const int t = lane & 3;        // thread-in-group 0..3
    const int warpM = wid & 3;     // 0..3  (M subtile of 32)
    const int warpN = wid >> 2;    // 0..1  (N subtile of 64)
    const int row0 = blockIdx.y * 128;
    const int col0 = blockIdx.x * 128;

    const uint16_t* Ahi = (MODE == 0) ? g_xhi : g_yhi;
    const uint16_t* Alo = (MODE == 0) ? g_xlo : g_ylo;
    const uint16_t* Bhi = (MODE == 0) ? g_wta_hi : g_wtp_hi;
    const uint16_t* Blo = (MODE == 0) ? g_wta_lo : g_wtp_lo;

    float acc[2][8][4];
    #pragma unroll
    for (int mt = 0; mt < 2; mt++)
        #pragma unroll
        for (int nt = 0; nt < 8; nt++)
            #pragma unroll
            for (int j = 0; j < 4; j++) acc[mt][nt][j] = 0.f;

    preload_stage(sb, Ahi, Alo, Bhi, Blo, row0, col0, 0, tid);
    CP_COMMIT();

    const char* smc = smem;
    // per-warp base byte offsets within a stage
    const uint32_t aRow = (uint32_t)((warpM * 32 + g) * ROWB);       // A row for this lane
    const uint32_t bRow = (uint32_t)((warpN * 64 + g) * ROWB);       // B row base

    for (int s = 0; s < NSTG; s++) {
        if (s + 1 < NSTG) {
            preload_stage(sb + ((s + 1) & 1) * STAGE_B, Ahi, Alo, Bhi, Blo,
                          row0, col0, (s + 1) * BK, tid);
            CP_COMMIT();
            CP_WAIT(1);
        } else {
            CP_WAIT(0);
        }
        __syncthreads();

        const char* stg = smc + (s & 1) * STAGE_B;
        const char* Ah = stg + 0 * MAT_B;
        const char* Al = stg + 1 * MAT_B;
        const char* Bh = stg + 2 * MAT_B;
        const char* Bl = stg + 3 * MAT_B;

        #pragma unroll
        for (int ks = 0; ks < 2; ks++) {
            const uint32_t kOff = (uint32_t)(ks * 32 + t * 4);
            uint32_t ah[2][4], al[2][4];
            #pragma unroll
            for (int mt = 0; mt < 2; mt++) {
                uint32_t ro = aRow + (uint32_t)(mt * 16 * ROWB) + kOff;
                ah[mt][0] = *(const uint32_t*)(Ah + ro);
                ah[mt][1] = *(const uint32_t*)(Ah + ro + 8 * ROWB);
                ah[mt][2] = *(const uint32_t*)(Ah + ro + 16);
                ah[mt][3] = *(const uint32_t*)(Ah + ro + 8 * ROWB + 16);
                al[mt][0] = *(const uint32_t*)(Al + ro);
                al[mt][1] = *(const uint32_t*)(Al + ro + 8 * ROWB);
                al[mt][2] = *(const uint32_t*)(Al + ro + 16);
                al[mt][3] = *(const uint32_t*)(Al + ro + 8 * ROWB + 16);
            }
            #pragma unroll
            for (int nt = 0; nt < 8; nt++) {
                uint32_t ro = bRow + (uint32_t)(nt * 8 * ROWB) + kOff;
                uint32_t bh[2], bl[2];
                bh[0] = *(const uint32_t*)(Bh + ro);
                bh[1] = *(const uint32_t*)(Bh + ro + 16);
                bl[0] = *(const uint32_t*)(Bl + ro);
                bl[1] = *(const uint32_t*)(Bl + ro + 16);
                #pragma unroll
                for (int mt = 0; mt < 2; mt++) {
                    mma16816(acc[mt][nt], ah[mt], bh);   // hi*hi
                    mma16816(acc[mt][nt], ah[mt], bl);   // hi*lo
                    mma16816(acc[mt][nt], al[mt], bh);   // lo*hi
                }
            }
        }
        __syncthreads();
    }

    // epilogue
    #pragma unroll
    for (int mt = 0; mt < 2; mt++) {
        #pragma unroll
        for (int nt = 0; nt < 8; nt++) {
            #pragma unroll
            for (int half = 0; half < 2; half++) {          // d0/d1 then d2/d3
                int m = row0 + warpM * 32 + mt * 16 + g + half * 8;
                int n = col0 + warpN * 64 + nt * 8 + t * 2;
                float v0 = acc[mt][nt][half * 2 + 0] + bias[n];
                float v1 = acc[mt][nt][half * 2 + 1] + bias[n + 1];
                if (MODE == 0) {
                    int b_ = m >> 11;
                    int tt = m & 2047;
                    int which = n >> 10;
                    int cc = n & 1023;
                    int h = cc >> 6;
                    int d = cc & 63;
                    float* dst = (which == 0) ? g_q : (which == 1) ? g_k : g_v;
                    float* p = dst + (((size_t)b_ * Hh + h) * Tt + tt) * Dd + d;
                    p[0] = v0; p[1] = v1;
                } else {
                    float* p = out + (size_t)m * Cc + n;
                    p[0] = v0; p[1] = v1;
                }
            }
        }
    }
}

// ---------------------------------------------------------------------------
// Flash attention (fp32) — unchanged (R1 passing version)
// ---------------------------------------------------------------------------
__global__ __launch_bounds__(128, 2)
void attn_kernel()
{
    __shared__ float4 Ks[64][16];
    __shared__ float4 Vs[64][16];

    const int tid = threadIdx.x;
    const int qi  = blockIdx.x * 128 + tid;
    const int bh  = blockIdx.y;

    const float* __restrict__ qptr  = g_q + ((size_t)bh * Tt + qi) * Dd;
    const float* __restrict__ kbase = g_k + (size_t)bh * Tt * Dd;
    const float* __restrict__ vbase = g_v + (size_t)bh * Tt * Dd;

    float q[64];
    #pragma unroll
    for (int d = 0; d < 64; d++) q[d] = qptr[d] * 0.125f;

    float o[64];
    #pragma unroll
    for (int d = 0; d < 64; d++) o[d] = 0.f;
    float mval = -1e30f;
    float lsum = 0.f;

    for (int kt = 0; kt < Tt; kt += 64) {
        __syncthreads();
        #pragma unroll
        for (int i = 0; i < 8; i++) {
            int s = tid + 128 * i;
            int r = s >> 4;
            int c = s & 15;
            Ks[r][c] = ((const float4*)(kbase + (size_t)(kt + r) * Dd))[c];
            Vs[r][c] = ((const float4*)(vbase + (size_t)(kt + r) * Dd))[c];
        }
        __syncthreads();

        #pragma unroll 1
        for (int cch = 0; cch < 4; cch++) {
            float s_[16];
            #pragma unroll
            for (int j = 0; j < 16; j++) {
                float acc0 = 0.f, acc1 = 0.f;
                #pragma unroll
                for (int d4 = 0; d4 < 16; d4++) {
                    float4 kk = Ks[cch * 16 + j][d4];
                    acc0 += q[d4*4+0] * kk.x;
                    acc1 += q[d4*4+1] * kk.y;
                    acc0 += q[d4*4+2] * kk.z;
                    acc1 += q[d4*4+3] * kk.w;
                }
                s_[j] = acc0 + acc1;
            }
            float mt = mval;
            #pragma unroll
            for (int j = 0; j < 16; j++) mt = fmaxf(mt, s_[j]);
            float fac = __expf(mval - mt);
            mval = mt;
            lsum *= fac;
            #pragma unroll
            for (int d = 0; d < 64; d++) o[d] *= fac;
            #pragma unroll
            for (int j = 0; j < 16; j++) {
                float p = __expf(s_[j] - mval);
                lsum += p;
                #pragma unroll
                for (int d4 = 0; d4 < 16; d4++) {
                    float4 vv = Vs[cch * 16 + j][d4];
                    o[d4*4+0] += p * vv.x;
                    o[d4*4+1] += p * vv.y;
                    o[d4*4+2] += p * vv.z;
                    o[d4*4+3] += p * vv.w;
                }
            }
        }
    }

    const int b_ = bh >> 4;
    const int h  = bh & 15;
    const float inv = 1.f / lsum;
    float* yp = g_y + ((size_t)b_ * Tt + qi) * Cc + h * 64;
    #pragma unroll
    for (int d = 0; d < 64; d++) yp[d] = o[d] * inv;
}

// ---------------------------------------------------------------------------
extern "C" void kernel_launch(void* const* d_in, const int* in_sizes, int n_in,
                              void* d_out, int out_size)
{
    const float* x      = (const float*)d_in[0];
    const float* W_attn = (const float*)d_in[1];
    const float* b_attn = (const float*)d_in[2];
    const float* W_proj = (const float*)d_in[3];
    const float* b_proj = (const float*)d_in[4];
    float* out = (float*)d_out;

    cudaFuncSetAttribute(mma_gemm_kernel<0>, cudaFuncAttributeMaxDynamicSharedMemorySize, GEMM_SMEM);
    cudaFuncSetAttribute(mma_gemm_kernel<1>, cudaFuncAttributeMaxDynamicSharedMemorySize, GEMM_SMEM);

    // prep: bf16 splits + weight transposes
    split_kernel<<<4096, 256>>>(x);
    transpose_split_kernel<0, NQKV><<<dim3(NQKV / 32, Kdim / 32), dim3(32, 8)>>>(W_attn);
    transpose_split_kernel<1, Cc><<<dim3(Cc / 32, Kdim / 32), dim3(32, 8)>>>(W_proj);

    // 1) QKV projection (tensor cores) + head scatter
    mma_gemm_kernel<0><<<dim3(NQKV / 128, Mrows / 128), 256, GEMM_SMEM>>>(b_attn, nullptr);

    // 2) attention (fp32)
    attn_kernel<<<dim3(Tt / 128, Bb * Hh), 128>>>();

    // 3) split y, then output projection (tensor cores)
    split_kernel<<<4096, 256>>>(nullptr);
    mma_gemm_kernel<1><<<dim3(Cc / 128, Mrows / 128), 256, GEMM_SMEM>>>(b_proj, out);
}

// round 4
// speedup vs baseline: 4.1802x; 2.9060x over previous
#include <cuda_runtime.h>
#include <cuda_bf16.h>
#include <cstdint>

#define Bb 4
#define Tt 2048
#define Cc 1024
#define Hh 16
#define Dd 64
#define Kdim 1024
#define NQKV 3072
#define Mrows 8192

// ---------------------------------------------------------------------------
// scratch (__device__ globals; allocation-free)
// ---------------------------------------------------------------------------
__device__ uint16_t g_xhi[(size_t)Mrows*Kdim];
__device__ uint16_t g_xlo[(size_t)Mrows*Kdim];
__device__ uint16_t g_yhi[(size_t)Mrows*Kdim];
__device__ uint16_t g_ylo[(size_t)Mrows*Kdim];
__device__ uint16_t g_wta_hi[(size_t)NQKV*Kdim];
__device__ uint16_t g_wta_lo[(size_t)NQKV*Kdim];
__device__ uint16_t g_wtp_hi[(size_t)Cc*Kdim];
__device__ uint16_t g_wtp_lo[(size_t)Cc*Kdim];

// attention operands, [b,h,t,d] bf16
__device__ uint16_t g_qhi[(size_t)Bb*Hh*Tt*Dd];   // pre-scaled by 1/8, split hi
__device__ uint16_t g_qlo[(size_t)Bb*Hh*Tt*Dd];
__device__ uint16_t g_kk [(size_t)Bb*Hh*Tt*Dd];   // raw bf16
__device__ uint16_t g_vhi[(size_t)Bb*Hh*Tt*Dd];
__device__ uint16_t g_vlo[(size_t)Bb*Hh*Tt*Dd];

// ---------------------------------------------------------------------------
// helpers
// ---------------------------------------------------------------------------
__device__ __forceinline__ uint32_t smem_u32(const void* p) {
    uint32_t a;
    asm("{ .reg .u64 t; cvta.to.shared.u64 t, %1; cvt.u32.u64 %0, t; }" : "=r"(a) : "l"(p));
    return a;
}
__device__ __forceinline__ void cp16(uint32_t dst, const void* src) {
    asm volatile("cp.async.cg.shared.global [%0], [%1], 16;" :: "r"(dst), "l"(src));
}
#define CP_COMMIT() asm volatile("cp.async.commit_group;" ::: "memory")
#define CP_WAIT(n)  asm volatile("cp.async.wait_group %0;" :: "n"(n) : "memory")

__device__ __forceinline__ void mma16816(float d[4], const uint32_t a[4], const uint32_t b[2]) {
    asm volatile(
        "mma.sync.aligned.m16n8k16.row.col.f32.bf16.bf16.f32 "
        "{%0,%1,%2,%3}, {%4,%5,%6,%7}, {%8,%9}, {%0,%1,%2,%3};"
        : "+f"(d[0]), "+f"(d[1]), "+f"(d[2]), "+f"(d[3])
        : "r"(a[0]), "r"(a[1]), "r"(a[2]), "r"(a[3]), "r"(b[0]), "r"(b[1]));
}
__device__ __forceinline__ void ldsm_x4(uint32_t r[4], uint32_t a) {
    asm volatile("ldmatrix.sync.aligned.m8n8.x4.shared.b16 {%0,%1,%2,%3}, [%4];"
        : "=r"(r[0]), "=r"(r[1]), "=r"(r[2]), "=r"(r[3]) : "r"(a));
}
__device__ __forceinline__ void ldsm_x4_t(uint32_t r[4], uint32_t a) {
    asm volatile("ldmatrix.sync.aligned.m8n8.x4.trans.shared.b16 {%0,%1,%2,%3}, [%4];"
        : "=r"(r[0]), "=r"(r[1]), "=r"(r[2]), "=r"(r[3]) : "r"(a));
}

__device__ __forceinline__ void split_one(float v, uint16_t& h, uint16_t& l) {
    __nv_bfloat16 hb = __float2bfloat16(v);
    float rem = v - __bfloat162float(hb);
    __nv_bfloat16 lb = __float2bfloat16(rem);
    h = *reinterpret_cast<uint16_t*>(&hb);
    l = *reinterpret_cast<uint16_t*>(&lb);
}
__device__ __forceinline__ uint32_t pack_bf16(float a, float b) {
    __nv_bfloat162 h2 = __float22bfloat162_rn(make_float2(a, b));
    return *reinterpret_cast<uint32_t*>(&h2);
}

// ---------------------------------------------------------------------------
// prep kernels
// ---------------------------------------------------------------------------
__global__ void split_kernel(const float* __restrict__ src) {
    size_t n = (size_t)Mrows * Kdim;
    for (size_t i = blockIdx.x * (size_t)blockDim.x + threadIdx.x; i < n;
         i += (size_t)gridDim.x * blockDim.x)
        split_one(src[i], g_xhi[i], g_xlo[i]);
}

template<int WHICH, int N>
__global__ void transpose_split_kernel(const float* __restrict__ W) {
    uint16_t* hi = (WHICH == 0) ? g_wta_hi : g_wtp_hi;
    uint16_t* lo = (WHICH == 0) ? g_wta_lo : g_wtp_lo;
    __shared__ float t[32][33];
    int n0 = blockIdx.x * 32, k0 = blockIdx.y * 32;
    #pragma unroll
    for (int i = 0; i < 4; i++)
        t[threadIdx.y + 8 * i][threadIdx.x] = W[(size_t)(k0 + threadIdx.y + 8 * i) * N + n0 + threadIdx.x];
    __syncthreads();
    #pragma unroll
    for (int i = 0; i < 4; i++) {
        int n = n0 + threadIdx.y + 8 * i;
        int k = k0 + threadIdx.x;
        uint16_t h, l;
        split_one(t[threadIdx.x][threadIdx.y + 8 * i], h, l);
        hi[(size_t)n * Kdim + k] = h;
        lo[(size_t)n * Kdim + k] = l;
    }
}

// ---------------------------------------------------------------------------
// mma.sync GEMM (3-pass bf16 split), 128x128 block, BK=32, 8 warps (4Mx2N)
// MODE 0: A=x(split), B=W_attn^T -> split/scatter into q/k/v bf16 buffers
// MODE 1: A=y(split), B=W_proj^T -> fp32 out
// ---------------------------------------------------------------------------
#define BK 32
#define NSTG (Kdim / BK)
#define ROWB 80
#define MAT_B (128 * ROWB)
#define STAGE_B (4 * MAT_B)
#define GEMM_SMEM (2 * STAGE_B)

__device__ __forceinline__ void preload_stage(uint32_t st,
        const uint16_t* __restrict__ Ahi, const uint16_t* __restrict__ Alo,
        const uint16_t* __restrict__ Bhi, const uint16_t* __restrict__ Blo,
        int row0, int col0, int kc, int tid)
{
    #pragma unroll
    for (int i = 0; i < 2; i++) {
        int idx = tid + i * 256;
        int r = idx >> 2;
        int c = idx & 3;
        uint32_t off = (uint32_t)(r * ROWB + c * 16);
        size_t gA = (size_t)(row0 + r) * Kdim + kc + c * 8;
        size_t gB = (size_t)(col0 + r) * Kdim + kc + c * 8;
        cp16(st + 0 * MAT_B + off, Ahi + gA);
        cp16(st + 1 * MAT_B + off, Alo + gA);
        cp16(st + 2 * MAT_B + off, Bhi + gB);
        cp16(st + 3 * MAT_B + off, Blo + gB);
    }
}

template<int MODE>
__global__ void __launch_bounds__(256) mma_gemm_kernel(const float* __restrict__ bias,
                                                       float* __restrict__ out)
{
    extern __shared__ char smem[];
    const uint32_t sb = smem_u32(smem);
    const int tid  = threadIdx.x;
    const int wid  = tid >> 5;
    const int lane = tid & 31;
    const int g = lane >> 2;
    const int t = lane & 3;
    const int warpM = wid & 3;
    const int warpN = wid >> 2;
    const int row0 = blockIdx.y * 128;
    const int col0 = blockIdx.x * 128;

    const uint16_t* Ahi = (MODE == 0) ? g_xhi : g_yhi;
    const uint16_t* Alo = (MODE == 0) ? g_xlo : g_ylo;
    const uint16_t* Bhi = (MODE == 0) ? g_wta_hi : g_wtp_hi;
    const uint16_t* Blo = (MODE == 0) ? g_wta_lo : g_wtp_lo;

    float acc[2][8][4];
    #pragma unroll
    for (int mt = 0; mt < 2; mt++)
        #pragma unroll
        for (int nt = 0; nt < 8; nt++)
            #pragma unroll
            for (int j = 0; j < 4; j++) acc[mt][nt][j] = 0.f;

    preload_stage(sb, Ahi, Alo, Bhi, Blo, row0, col0, 0, tid);
    CP_COMMIT();

    const char* smc = smem;
    const uint32_t aRow = (uint32_t)((warpM * 32 + g) * ROWB);
    const uint32_t bRow = (uint32_t)((warpN * 64 + g) * ROWB);

    for (int s = 0; s < NSTG; s++) {
        if (s + 1 < NSTG) {
            preload_stage(sb + ((s + 1) & 1) * STAGE_B, Ahi, Alo, Bhi, Blo,
                          row0, col0, (s + 1) * BK, tid);
            CP_COMMIT();
            CP_WAIT(1);
        } else {
            CP_WAIT(0);
        }
        __syncthreads();

        const char* stg = smc + (s & 1) * STAGE_B;
        const char* Ah = stg + 0 * MAT_B;
        const char* Al = stg + 1 * MAT_B;
        const char* Bh = stg + 2 * MAT_B;
        const char* Bl = stg + 3 * MAT_B;

        #pragma unroll
        for (int ks = 0; ks < 2; ks++) {
            const uint32_t kOff = (uint32_t)(ks * 32 + t * 4);
            uint32_t ah[2][4], al[2][4];
            #pragma unroll
            for (int mt = 0; mt < 2; mt++) {
                uint32_t ro = aRow + (uint32_t)(mt * 16 * ROWB) + kOff;
                ah[mt][0] = *(const uint32_t*)(Ah + ro);
                ah[mt][1] = *(const uint32_t*)(Ah + ro + 8 * ROWB);
                ah[mt][2] = *(const uint32_t*)(Ah + ro + 16);
                ah[mt][3] = *(const uint32_t*)(Ah + ro + 8 * ROWB + 16);
                al[mt][0] = *(const uint32_t*)(Al + ro);
                al[mt][1] = *(const uint32_t*)(Al + ro + 8 * ROWB);
                al[mt][2] = *(const uint32_t*)(Al + ro + 16);
                al[mt][3] = *(const uint32_t*)(Al + ro + 8 * ROWB + 16);
            }
            #pragma unroll
            for (int nt = 0; nt < 8; nt++) {
                uint32_t ro = bRow + (uint32_t)(nt * 8 * ROWB) + kOff;
                uint32_t bh[2], bl[2];
                bh[0] = *(const uint32_t*)(Bh + ro);
                bh[1] = *(const uint32_t*)(Bh + ro + 16);
                bl[0] = *(const uint32_t*)(Bl + ro);
                bl[1] = *(const uint32_t*)(Bl + ro + 16);
                #pragma unroll
                for (int mt = 0; mt < 2; mt++) {
                    mma16816(acc[mt][nt], ah[mt], bh);
                    mma16816(acc[mt][nt], ah[mt], bl);
                    mma16816(acc[mt][nt], al[mt], bh);
                }
            }
        }
        __syncthreads();
    }

    #pragma unroll
    for (int mt = 0; mt < 2; mt++) {
        #pragma unroll
        for (int nt = 0; nt < 8; nt++) {
            #pragma unroll
            for (int half = 0; half < 2; half++) {
                int m = row0 + warpM * 32 + mt * 16 + g + half * 8;
                int n = col0 + warpN * 64 + nt * 8 + t * 2;
                float v0 = acc[mt][nt][half * 2 + 0] + bias[n];
                float v1 = acc[mt][nt][half * 2 + 1] + bias[n + 1];
                if (MODE == 0) {
                    int b_ = m >> 11;
                    int tt = m & 2047;
                    int which = n >> 10;
                    int cc = n & 1023;
                    int h = cc >> 6;
                    int d = cc & 63;
                    size_t base = (((size_t)b_ * Hh + h) * Tt + tt) * Dd + d;
                    if (which == 0) {
                        uint16_t h0, l0, h1, l1;
                        split_one(v0 * 0.125f, h0, l0);
                        split_one(v1 * 0.125f, h1, l1);
                        *(uint32_t*)&g_qhi[base] = (uint32_t)h0 | ((uint32_t)h1 << 16);
                        *(uint32_t*)&g_qlo[base] = (uint32_t)l0 | ((uint32_t)l1 << 16);
                    } else if (which == 1) {
                        *(uint32_t*)&g_kk[base] = pack_bf16(v0, v1);
                    } else {
                        uint16_t h0, l0, h1, l1;
                        split_one(v0, h0, l0);
                        split_one(v1, h1, l1);
                        *(uint32_t*)&g_vhi[base] = (uint32_t)h0 | ((uint32_t)h1 << 16);
                        *(uint32_t*)&g_vlo[base] = (uint32_t)l0 | ((uint32_t)l1 << 16);
                    }
                } else {
                    float* p = out + (size_t)m * Cc + n;
                    p[0] = v0; p[1] = v1;
                }
            }
        }
    }
}

// ---------------------------------------------------------------------------
// Flash attention via mma.sync (FA2 pattern)
// grid (Tt/128, Bb*Hh), 256 threads = 8 warps, warp = 16 q-rows x all keys.
// K-tile = 64 keys. S: 2-pass (Qhi,Qlo)xK. PV: P(bf16) x (Vhi,Vlo).
// SMEM rows padded to 72 bf16 (144B) -> conflict-free LDS/LDSM.
// ---------------------------------------------------------------------------
#define TK 64
#define NTILE (Tt / TK)             // 32
#define AROW 144                    // padded row bytes
#define K_OFF 0
#define VH_OFF (64 * AROW)          // 9216
#define VL_OFF (128 * AROW)         // 18432
#define STG_B (192 * AROW)          // 27648
#define ATT_SMEM (2 * STG_B)        // 55296

__global__ void __launch_bounds__(256) attn_mma_kernel()
{
    extern __shared__ char smem[];
    const uint32_t sb = smem_u32(smem);
    const int tid  = threadIdx.x;
    const int w    = tid >> 5;
    const int lane = tid & 31;
    const int g = lane >> 2;
    const int t = lane & 3;
    const int q0 = blockIdx.x * 128;
    const int bh = blockIdx.y;

    const size_t seqBase = (size_t)bh * Tt * Dd;

    // ---- prologue: load Q tile (hi/lo) into smem, extract fragments ----
    #pragma unroll
    for (int j = 0; j < 4; j++) {
        int idx = tid + j * 256;          // 0..1023
        int r = idx >> 3, c = idx & 7;
        size_t gsrc = seqBase + (size_t)(q0 + r) * Dd + c * 8;
        *(uint4*)(smem + r * AROW + c * 16)          = *(const uint4*)(g_qhi + gsrc);
        *(uint4*)(smem + VL_OFF + r * AROW + c * 16) = *(const uint4*)(g_qlo + gsrc);
    }
    __syncthreads();

    uint32_t qh[4][4], ql[4][4];
    {
        uint32_t qrow = (uint32_t)(w * 16 + (lane & 7) + ((lane >> 3) & 1) * 8);
        uint32_t coff = (uint32_t)(((lane >> 4) & 1) * 16);
        #pragma unroll
        for (int kf = 0; kf < 4; kf++) {
            ldsm_x4(qh[kf], sb + qrow * AROW + kf * 32 + coff);
            ldsm_x4(ql[kf], sb + VL_OFF + qrow * AROW + kf * 32 + coff);
        }
    }
    __syncthreads();

    // ---- state ----
    float oacc[8][4];
    #pragma unroll
    for (int nf = 0; nf < 8; nf++)
        #pragma unroll
        for (int j = 0; j < 4; j++) oacc[nf][j] = 0.f;
    float m0 = -1e30f, m1 = -1e30f, l0 = 0.f, l1 = 0.f;

    // ---- stage 0 ----
    {
        uint32_t st = sb;
        #pragma unroll
        for (int j = 0; j < 2; j++) {
            int idx = tid + j * 256;
            int r = idx >> 3, c = idx & 7;
            uint32_t off = (uint32_t)(r * AROW + c * 16);
            size_t gsrc = seqBase + (size_t)r * Dd + c * 8;
            cp16(st + K_OFF + off,  g_kk  + gsrc);
            cp16(st + VH_OFF + off, g_vhi + gsrc);
            cp16(st + VL_OFF + off, g_vlo + gsrc);
        }
        CP_COMMIT();
    }

    for (int kt = 0; kt < NTILE; kt++) {
        if (kt + 1 < NTILE) {
            uint32_t st = sb + ((kt + 1) & 1) * STG_B;
            #pragma unroll
            for (int j = 0; j < 2; j++) {
                int idx = tid + j * 256;
                int r = idx >> 3, c = idx & 7;
                uint32_t off = (uint32_t)(r * AROW + c * 16);
                size_t gsrc = seqBase + (size_t)((kt + 1) * TK + r) * Dd + c * 8;
                cp16(st + K_OFF + off,  g_kk  + gsrc);
                cp16(st + VH_OFF + off, g_vhi + gsrc);
                cp16(st + VL_OFF + off, g_vlo + gsrc);
            }
            CP_COMMIT();
            CP_WAIT(1);
        } else {
            CP_WAIT(0);
        }
        __syncthreads();

        const char* stg = smem + (kt & 1) * STG_B;

        // ---- S = Q K^T (2 passes) ----
        float sacc[8][4];
        #pragma unroll
        for (int nf = 0; nf < 8; nf++)
            #pragma unroll
            for (int j = 0; j < 4; j++) sacc[nf][j] = 0.f;

        #pragma unroll
        for (int kf = 0; kf < 4; kf++) {
            uint32_t bf[8][2];
            #pragma unroll
            for (int nf = 0; nf < 8; nf++) {
                const char* p = stg + K_OFF + (nf * 8 + g) * AROW + kf * 32 + t * 4;
                bf[nf][0] = *(const uint32_t*)(p);
                bf[nf][1] = *(const uint32_t*)(p + 16);
            }
            #pragma unroll
            for (int nf = 0; nf < 8; nf++) mma16816(sacc[nf], qh[kf], bf[nf]);
            #pragma unroll
            for (int nf = 0; nf < 8; nf++) mma16816(sacc[nf], ql[kf], bf[nf]);
        }

        // ---- online softmax ----
        float rm0 = sacc[0][0], rm1 = sacc[0][2];
        #pragma unroll
        for (int nf = 0; nf < 8; nf++) {
            rm0 = fmaxf(rm0, fmaxf(sacc[nf][0], sacc[nf][1]));
            rm1 = fmaxf(rm1, fmaxf(sacc[nf][2], sacc[nf][3]));
        }
        rm0 = fmaxf(rm0, __shfl_xor_sync(0xffffffffu, rm0, 1));
        rm0 = fmaxf(rm0, __shfl_xor_sync(0xffffffffu, rm0, 2));
        rm1 = fmaxf(rm1, __shfl_xor_sync(0xffffffffu, rm1, 1));
        rm1 = fmaxf(rm1, __shfl_xor_sync(0xffffffffu, rm1, 2));

        float mn0 = fmaxf(m0, rm0), mn1 = fmaxf(m1, rm1);
        float al0 = __expf(m0 - mn0), al1 = __expf(m1 - mn1);
        m0 = mn0; m1 = mn1;

        float ls0 = 0.f, ls1 = 0.f;
        #pragma unroll
        for (int nf = 0; nf < 8; nf++) {
            sacc[nf][0] = __expf(sacc[nf][0] - m0);
            sacc[nf][1] = __expf(sacc[nf][1] - m0);
            sacc[nf][2] = __expf(sacc[nf][2] - m1);
            sacc[nf][3] = __expf(sacc[nf][3] - m1);
            ls0 += sacc[nf][0] + sacc[nf][1];
            ls1 += sacc[nf][2] + sacc[nf][3];
        }
        ls0 += __shfl_xor_sync(0xffffffffu, ls0, 1);
        ls0 += __shfl_xor_sync(0xffffffffu, ls0, 2);
        ls1 += __shfl_xor_sync(0xffffffffu, ls1, 1);
        ls1 += __shfl_xor_sync(0xffffffffu, ls1, 2);
        l0 = l0 * al0 + ls0;
        l1 = l1 * al1 + ls1;

        #pragma unroll
        for (int nf = 0; nf < 8; nf++) {
            oacc[nf][0] *= al0; oacc[nf][1] *= al0;
            oacc[nf][2] *= al1; oacc[nf][3] *= al1;
        }

        // pack P fragments (bf16)
        uint32_t pa[4][4];
        #pragma unroll
        for (int k2 = 0; k2 < 4; k2++) {
            pa[k2][0] = pack_bf16(sacc[2*k2][0],   sacc[2*k2][1]);
            pa[k2][1] = pack_bf16(sacc[2*k2][2],   sacc[2*k2][3]);
            pa[k2][2] = pack_bf16(sacc[2*k2+1][0], sacc[2*k2+1][1]);
            pa[k2][3] = pack_bf16(sacc[2*k2+1][2], sacc[2*k2+1][3]);
        }

        // ---- O += P V (V hi + lo passes), V fragments via ldmatrix.trans ----
        const uint32_t stgU = sb + (kt & 1) * STG_B;
        #pragma unroll
        for (int k2 = 0; k2 < 4; k2++) {
            uint32_t vrow = (uint32_t)(k2 * 16 + ((lane >> 3) & 1) * 8 + (lane & 7));
            uint32_t lhalf = (uint32_t)(((lane >> 4) & 1) * 16);
            #pragma unroll
            for (int np = 0; np < 4; np++) {
                uint32_t addr = stgU + vrow * AROW + np * 32 + lhalf;
                uint32_t rh[4], rl[4];
                ldsm_x4_t(rh, addr + VH_OFF);
                mma16816(oacc[2*np],   pa[k2], rh + 0);
                mma16816(oacc[2*np+1], pa[k2], rh + 2);
                ldsm_x4_t(rl, addr + VL_OFF);
                mma16816(oacc[2*np],   pa[k2], rl + 0);
                mma16816(oacc[2*np+1], pa[k2], rl + 2);
            }
        }
        __syncthreads();
    }

    // ---- epilogue: O/l -> smem -> split bf16 y (coalesced) ----
    float* Osm = (float*)smem;
    const float inv0 = 1.f / l0, inv1 = 1.f / l1;
    #pragma unroll
    for (int nf = 0; nf < 8; nf++) {
        int c = nf * 8 + t * 2;
        Osm[(w * 16 + g)     * 72 + c]     = oacc[nf][0] * inv0;
        Osm[(w * 16 + g)     * 72 + c + 1] = oacc[nf][1] * inv0;
        Osm[(w * 16 + 8 + g) * 72 + c]     = oacc[nf][2] * inv1;
        Osm[(w * 16 + 8 + g) * 72 + c + 1] = oacc[nf][3] * inv1;
    }
    __syncthreads();

    {
        int r = tid >> 1, half = tid & 1;
        int b_ = bh >> 4, h = bh & 15;
        size_t base = ((size_t)b_ * Tt + q0 + r) * Cc + h * 64 + half * 32;
        uint16_t hb[32], lb[32];
        #pragma unroll
        for (int i = 0; i < 32; i++)
            split_one(Osm[r * 72 + half * 32 + i], hb[i], lb[i]);
        #pragma unroll
        for (int c4 = 0; c4 < 4; c4++) {
            *(uint4*)(g_yhi + base + c4 * 8) = *(uint4*)(hb + c4 * 8);
            *(uint4*)(g_ylo + base + c4 * 8) = *(uint4*)(lb + c4 * 8);
        }
    }
}

// ---------------------------------------------------------------------------
extern "C" void kernel_launch(void* const* d_in, const int* in_sizes, int n_in,
                              void* d_out, int out_size)
{
    const float* x      = (const float*)d_in[0];
    const float* W_attn = (const float*)d_in[1];
    const float* b_attn = (const float*)d_in[2];
    const float* W_proj = (const float*)d_in[3];
    const float* b_proj = (const float*)d_in[4];
    float* out = (float*)d_out;

    cudaFuncSetAttribute(mma_gemm_kernel<0>, cudaFuncAttributeMaxDynamicSharedMemorySize, GEMM_SMEM);
    cudaFuncSetAttribute(mma_gemm_kernel<1>, cudaFuncAttributeMaxDynamicSharedMemorySize, GEMM_SMEM);
    cudaFuncSetAttribute(attn_mma_kernel, cudaFuncAttributeMaxDynamicSharedMemorySize, ATT_SMEM);

    split_kernel<<<4096, 256>>>(x);
    transpose_split_kernel<0, NQKV><<<dim3(NQKV / 32, Kdim / 32), dim3(32, 8)>>>(W_attn);
    transpose_split_kernel<1, Cc><<<dim3(Cc / 32, Kdim / 32), dim3(32, 8)>>>(W_proj);

    mma_gemm_kernel<0><<<dim3(NQKV / 128, Mrows / 128), 256, GEMM_SMEM>>>(b_attn, nullptr);

    attn_mma_kernel<<<dim3(Tt / 128, Bb * Hh), 256, ATT_SMEM>>>();

    mma_gemm_kernel<1><<<dim3(Cc / 128, Mrows / 128), 256, GEMM_SMEM>>>(b_proj, out);
}

// round 6
// speedup vs baseline: 4.6149x; 1.1040x over previous
#include <cuda_runtime.h>
#include <cuda_bf16.h>
#include <cstdint>

#define Bb 4
#define Tt 2048
#define Cc 1024
#define Hh 16
#define Dd 64
#define Kdim 1024
#define NQKV 3072
#define Mrows 8192

// ---------------------------------------------------------------------------
// scratch (__device__ globals; allocation-free)
// ---------------------------------------------------------------------------
__device__ uint16_t g_xhi[(size_t)Mrows*Kdim];
__device__ uint16_t g_xlo[(size_t)Mrows*Kdim];
__device__ uint16_t g_yhi[(size_t)Mrows*Kdim];
__device__ uint16_t g_ylo[(size_t)Mrows*Kdim];
__device__ uint16_t g_wta_hi[(size_t)NQKV*Kdim];
__device__ uint16_t g_wta_lo[(size_t)NQKV*Kdim];
__device__ uint16_t g_wtp_hi[(size_t)Cc*Kdim];
__device__ uint16_t g_wtp_lo[(size_t)Cc*Kdim];

// attention operands, [b,h,t,d] bf16
__device__ uint16_t g_qhi[(size_t)Bb*Hh*Tt*Dd];   // pre-scaled by 1/8, split hi
__device__ uint16_t g_qlo[(size_t)Bb*Hh*Tt*Dd];
__device__ uint16_t g_kk [(size_t)Bb*Hh*Tt*Dd];   // raw bf16
__device__ uint16_t g_vhi[(size_t)Bb*Hh*Tt*Dd];
__device__ uint16_t g_vlo[(size_t)Bb*Hh*Tt*Dd];

// ---------------------------------------------------------------------------
// helpers
// ---------------------------------------------------------------------------
__device__ __forceinline__ uint32_t smem_u32(const void* p) {
    uint32_t a;
    asm("{ .reg .u64 t; cvta.to.shared.u64 t, %1; cvt.u32.u64 %0, t; }" : "=r"(a) : "l"(p));
    return a;
}
__device__ __forceinline__ void cp16(uint32_t dst, const void* src) {
    asm volatile("cp.async.cg.shared.global [%0], [%1], 16;" :: "r"(dst), "l"(src));
}
#define CP_COMMIT() asm volatile("cp.async.commit_group;" ::: "memory")
#define CP_WAIT(n)  asm volatile("cp.async.wait_group %0;" :: "n"(n) : "memory")

__device__ __forceinline__ void mma16816(float d[4], const uint32_t a[4], const uint32_t b[2]) {
    asm volatile(
        "mma.sync.aligned.m16n8k16.row.col.f32.bf16.bf16.f32 "
        "{%0,%1,%2,%3}, {%4,%5,%6,%7}, {%8,%9}, {%0,%1,%2,%3};"
        : "+f"(d[0]), "+f"(d[1]), "+f"(d[2]), "+f"(d[3])
        : "r"(a[0]), "r"(a[1]), "r"(a[2]), "r"(a[3]), "r"(b[0]), "r"(b[1]));
}
__device__ __forceinline__ void ldsm_x4(uint32_t r[4], uint32_t a) {
    asm volatile("ldmatrix.sync.aligned.m8n8.x4.shared.b16 {%0,%1,%2,%3}, [%4];"
        : "=r"(r[0]), "=r"(r[1]), "=r"(r[2]), "=r"(r[3]) : "r"(a));
}
__device__ __forceinline__ void ldsm_x4_t(uint32_t r[4], uint32_t a) {
    asm volatile("ldmatrix.sync.aligned.m8n8.x4.trans.shared.b16 {%0,%1,%2,%3}, [%4];"
        : "=r"(r[0]), "=r"(r[1]), "=r"(r[2]), "=r"(r[3]) : "r"(a));
}

__device__ __forceinline__ void split_one(float v, uint16_t& h, uint16_t& l) {
    __nv_bfloat16 hb = __float2bfloat16(v);
    float rem = v - __bfloat162float(hb);
    __nv_bfloat16 lb = __float2bfloat16(rem);
    h = *reinterpret_cast<uint16_t*>(&hb);
    l = *reinterpret_cast<uint16_t*>(&lb);
}
__device__ __forceinline__ uint32_t pack_bf16(float a, float b) {
    __nv_bfloat162 h2 = __float22bfloat162_rn(make_float2(a, b));
    return *reinterpret_cast<uint32_t*>(&h2);
}

// ---------------------------------------------------------------------------
// prep kernels
// ---------------------------------------------------------------------------
__global__ void split_kernel(const float* __restrict__ src) {
    size_t n = (size_t)Mrows * Kdim;
    for (size_t i = blockIdx.x * (size_t)blockDim.x + threadIdx.x; i < n;
         i += (size_t)gridDim.x * blockDim.x)
        split_one(src[i], g_xhi[i], g_xlo[i]);
}

template<int WHICH, int N>
__global__ void transpose_split_kernel(const float* __restrict__ W) {
    uint16_t* hi = (WHICH == 0) ? g_wta_hi : g_wtp_hi;
    uint16_t* lo = (WHICH == 0) ? g_wta_lo : g_wtp_lo;
    __shared__ float t[32][33];
    int n0 = blockIdx.x * 32, k0 = blockIdx.y * 32;
    #pragma unroll
    for (int i = 0; i < 4; i++)
        t[threadIdx.y + 8 * i][threadIdx.x] = W[(size_t)(k0 + threadIdx.y + 8 * i) * N + n0 + threadIdx.x];
    __syncthreads();
    #pragma unroll
    for (int i = 0; i < 4; i++) {
        int n = n0 + threadIdx.y + 8 * i;
        int k = k0 + threadIdx.x;
        uint16_t h, l;
        split_one(t[threadIdx.x][threadIdx.y + 8 * i], h, l);
        hi[(size_t)n * Kdim + k] = h;
        lo[(size_t)n * Kdim + k] = l;
    }
}

// ---------------------------------------------------------------------------
// mma.sync GEMM (3-pass bf16 split), 128x128 block, BK=32, 8 warps (4Mx2N)
// 2-stage cp.async pipeline (2 CTA/SM), ldmatrix fragment loads.
// ROWB=80 (=16*5): 16B-aligned rows (ldmatrix requirement) AND conflict-free
// LDSM phases (banks 20r mod 32 distinct over r=0..7).
// MODE 0: A=x(split), B=W_attn^T -> split/scatter into q/k/v bf16 buffers
// MODE 1: A=y(split), B=W_proj^T -> fp32 out
// ---------------------------------------------------------------------------
#define BK 32
#define NSTG (Kdim / BK)           // 32
#define ROWB 80
#define MAT_B (128 * ROWB)         // 10240
#define STAGE_B (4 * MAT_B)        // 40960
#define GEMM_SMEM (2 * STAGE_B)    // 81920

__device__ __forceinline__ void preload_stage(uint32_t st,
        const uint16_t* __restrict__ Ahi, const uint16_t* __restrict__ Alo,
        const uint16_t* __restrict__ Bhi, const uint16_t* __restrict__ Blo,
        int row0, int col0, int kc, int tid)
{
    #pragma unroll
    for (int i = 0; i < 2; i++) {
        int idx = tid + i * 256;
        int r = idx >> 2;
        int c = idx & 3;
        uint32_t off = (uint32_t)(r * ROWB + c * 16);
        size_t gA = (size_t)(row0 + r) * Kdim + kc + c * 8;
        size_t gB = (size_t)(col0 + r) * Kdim + kc + c * 8;
        cp16(st + 0 * MAT_B + off, Ahi + gA);
        cp16(st + 1 * MAT_B + off, Alo + gA);
        cp16(st + 2 * MAT_B + off, Bhi + gB);
        cp16(st + 3 * MAT_B + off, Blo + gB);
    }
}

template<int MODE>
__global__ void __launch_bounds__(256, 2) mma_gemm_kernel(const float* __restrict__ bias,
                                                          float* __restrict__ out)
{
    extern __shared__ char smem[];
    const uint32_t sb = smem_u32(smem);
    const int tid  = threadIdx.x;
    const int wid  = tid >> 5;
    const int lane = tid & 31;
    const int g = lane >> 2;
    const int t = lane & 3;
    const int warpM = wid & 3;
    const int warpN = wid >> 2;
    const int row0 = blockIdx.y * 128;
    const int col0 = blockIdx.x * 128;

    const uint16_t* Ahi = (MODE == 0) ? g_xhi : g_yhi;
    const uint16_t* Alo = (MODE == 0) ? g_xlo : g_ylo;
    const uint16_t* Bhi = (MODE == 0) ? g_wta_hi : g_wtp_hi;
    const uint16_t* Blo = (MODE == 0) ? g_wta_lo : g_wtp_lo;

    float acc[2][8][4];
    #pragma unroll
    for (int mt = 0; mt < 2; mt++)
        #pragma unroll
        for (int nt = 0; nt < 8; nt++)
            #pragma unroll
            for (int j = 0; j < 4; j++) acc[mt][nt][j] = 0.f;

    // ldmatrix lane addressing
    const uint32_t aRowIdx = (uint32_t)(((lane >> 3) & 1) * 8 + (lane & 7));
    const uint32_t aColOff = (uint32_t)(((lane >> 4) & 1) * 16);
    const uint32_t bRowIdx = (uint32_t)(((lane >> 4) & 1) * 8 + (lane & 7));
    const uint32_t bColOff = (uint32_t)(((lane >> 3) & 1) * 16);

    preload_stage(sb, Ahi, Alo, Bhi, Blo, row0, col0, 0, tid);
    CP_COMMIT();

    for (int s = 0; s < NSTG; s++) {
        if (s + 1 < NSTG) {
            preload_stage(sb + ((s + 1) & 1) * STAGE_B, Ahi, Alo, Bhi, Blo,
                          row0, col0, (s + 1) * BK, tid);
            CP_COMMIT();
            CP_WAIT(1);
        } else {
            CP_WAIT(0);
        }
        __syncthreads();

        const uint32_t stg = sb + (uint32_t)((s & 1) * STAGE_B);
        const uint32_t Ah = stg + 0 * MAT_B;
        const uint32_t Al = stg + 1 * MAT_B;
        const uint32_t Bh = stg + 2 * MAT_B;
        const uint32_t Bl = stg + 3 * MAT_B;

        #pragma unroll
        for (int ks = 0; ks < 2; ks++) {
            const uint32_t kByte = (uint32_t)(ks * 32);
            uint32_t ah[2][4], al[2][4];
            #pragma unroll
            for (int mt = 0; mt < 2; mt++) {
                uint32_t ra = (uint32_t)(warpM * 32 + mt * 16) + aRowIdx;
                ldsm_x4(ah[mt], Ah + ra * ROWB + kByte + aColOff);
                ldsm_x4(al[mt], Al + ra * ROWB + kByte + aColOff);
            }
            #pragma unroll
            for (int ntp = 0; ntp < 4; ntp++) {
                uint32_t rb = (uint32_t)(warpN * 64 + ntp * 16) + bRowIdx;
                uint32_t bh[4], bl[4];
                ldsm_x4(bh, Bh + rb * ROWB + kByte + bColOff);
                ldsm_x4(bl, Bl + rb * ROWB + kByte + bColOff);
                #pragma unroll
                for (int half = 0; half < 2; half++) {
                    #pragma unroll
                    for (int mt = 0; mt < 2; mt++) {
                        mma16816(acc[mt][ntp * 2 + half], ah[mt], bh + half * 2);
                        mma16816(acc[mt][ntp * 2 + half], ah[mt], bl + half * 2);
                        mma16816(acc[mt][ntp * 2 + half], al[mt], bh + half * 2);
                    }
                }
            }
        }
        __syncthreads();
    }

    #pragma unroll
    for (int mt = 0; mt < 2; mt++) {
        #pragma unroll
        for (int nt = 0; nt < 8; nt++) {
            #pragma unroll
            for (int half = 0; half < 2; half++) {
                int m = row0 + warpM * 32 + mt * 16 + g + half * 8;
                int n = col0 + warpN * 64 + nt * 8 + t * 2;
                float v0 = acc[mt][nt][half * 2 + 0] + bias[n];
                float v1 = acc[mt][nt][half * 2 + 1] + bias[n + 1];
                if (MODE == 0) {
                    int b_ = m >> 11;
                    int tt = m & 2047;
                    int which = n >> 10;
                    int cc = n & 1023;
                    int h = cc >> 6;
                    int d = cc & 63;
                    size_t base = (((size_t)b_ * Hh + h) * Tt + tt) * Dd + d;
                    if (which == 0) {
                        uint16_t h0, l0, h1, l1;
                        split_one(v0 * 0.125f, h0, l0);
                        split_one(v1 * 0.125f, h1, l1);
                        *(uint32_t*)&g_qhi[base] = (uint32_t)h0 | ((uint32_t)h1 << 16);
                        *(uint32_t*)&g_qlo[base] = (uint32_t)l0 | ((uint32_t)l1 << 16);
                    } else if (which == 1) {
                        *(uint32_t*)&g_kk[base] = pack_bf16(v0, v1);
                    } else {
                        uint16_t h0, l0, h1, l1;
                        split_one(v0, h0, l0);
                        split_one(v1, h1, l1);
                        *(uint32_t*)&g_vhi[base] = (uint32_t)h0 | ((uint32_t)h1 << 16);
                        *(uint32_t*)&g_vlo[base] = (uint32_t)l0 | ((uint32_t)l1 << 16);
                    }
                } else {
                    float* p = out + (size_t)m * Cc + n;
                    p[0] = v0; p[1] = v1;
                }
            }
        }
    }
}

// ---------------------------------------------------------------------------
// Flash attention via mma.sync (FA2 pattern)
// grid (Tt/128, Bb*Hh), 256 threads = 8 warps, warp = 16 q-rows x all keys.
// K-tile = 64 keys. S: 2-pass (Qhi,Qlo)xK (K frags via ldmatrix).
// PV: P(bf16) x (Vhi,Vlo) via ldmatrix.trans. AROW=144 (16-aligned).
// ---------------------------------------------------------------------------
#define TK 64
#define NTILE (Tt / TK)             // 32
#define AROW 144
#define K_OFF 0
#define VH_OFF (64 * AROW)
#define VL_OFF (128 * AROW)
#define STG_B (192 * AROW)          // 27648
#define ATT_SMEM (2 * STG_B)        // 55296

__global__ void __launch_bounds__(256, 2) attn_mma_kernel()
{
    extern __shared__ char smem[];
    const uint32_t sb = smem_u32(smem);
    const int tid  = threadIdx.x;
    const int w    = tid >> 5;
    const int lane = tid & 31;
    const int g = lane >> 2;
    const int t = lane & 3;
    const int q0 = blockIdx.x * 128;
    const int bh = blockIdx.y;

    const size_t seqBase = (size_t)bh * Tt * Dd;

    const uint32_t aRowIdx = (uint32_t)(((lane >> 3) & 1) * 8 + (lane & 7));
    const uint32_t aColOff = (uint32_t)(((lane >> 4) & 1) * 16);
    const uint32_t bRowIdx = (uint32_t)(((lane >> 4) & 1) * 8 + (lane & 7));
    const uint32_t bColOff = (uint32_t)(((lane >> 3) & 1) * 16);

    // ---- prologue: load Q tile (hi/lo) into smem, extract fragments ----
    #pragma unroll
    for (int j = 0; j < 4; j++) {
        int idx = tid + j * 256;
        int r = idx >> 3, c = idx & 7;
        size_t gsrc = seqBase + (size_t)(q0 + r) * Dd + c * 8;
        *(uint4*)(smem + r * AROW + c * 16)          = *(const uint4*)(g_qhi + gsrc);
        *(uint4*)(smem + VL_OFF + r * AROW + c * 16) = *(const uint4*)(g_qlo + gsrc);
    }
    __syncthreads();

    uint32_t qh[4][4], ql[4][4];
    {
        uint32_t qrow = (uint32_t)(w * 16) + aRowIdx;
        #pragma unroll
        for (int kf = 0; kf < 4; kf++) {
            ldsm_x4(qh[kf], sb + qrow * AROW + kf * 32 + aColOff);
            ldsm_x4(ql[kf], sb + VL_OFF + qrow * AROW + kf * 32 + aColOff);
        }
    }
    __syncthreads();

    float oacc[8][4];
    #pragma unroll
    for (int nf = 0; nf < 8; nf++)
        #pragma unroll
        for (int j = 0; j < 4; j++) oacc[nf][j] = 0.f;
    float m0 = -1e30f, m1 = -1e30f, l0 = 0.f, l1 = 0.f;

    // ---- stage 0 ----
    {
        uint32_t st = sb;
        #pragma unroll
        for (int j = 0; j < 2; j++) {
            int idx = tid + j * 256;
            int r = idx >> 3, c = idx & 7;
            uint32_t off = (uint32_t)(r * AROW + c * 16);
            size_t gsrc = seqBase + (size_t)r * Dd + c * 8;
            cp16(st + K_OFF + off,  g_kk  + gsrc);
            cp16(st + VH_OFF + off, g_vhi + gsrc);
            cp16(st + VL_OFF + off, g_vlo + gsrc);
        }
        CP_COMMIT();
    }

    for (int kt = 0; kt < NTILE; kt++) {
        if (kt + 1 < NTILE) {
            uint32_t st = sb + ((kt + 1) & 1) * STG_B;
            #pragma unroll
            for (int j = 0; j < 2; j++) {
                int idx = tid + j * 256;
                int r = idx >> 3, c = idx & 7;
                uint32_t off = (uint32_t)(r * AROW + c * 16);
                size_t gsrc = seqBase + (size_t)((kt + 1) * TK + r) * Dd + c * 8;
                cp16(st + K_OFF + off,  g_kk  + gsrc);
                cp16(st + VH_OFF + off, g_vhi + gsrc);
                cp16(st + VL_OFF + off, g_vlo + gsrc);
            }
            CP_COMMIT();
            CP_WAIT(1);
        } else {
            CP_WAIT(0);
        }
        __syncthreads();

        const uint32_t stgU = sb + (kt & 1) * STG_B;

        // ---- S = Q K^T (2 passes), K frags via ldmatrix ----
        float sacc[8][4];
        #pragma unroll
        for (int nf = 0; nf < 8; nf++)
            #pragma unroll
            for (int j = 0; j < 4; j++) sacc[nf][j] = 0.f;

        #pragma unroll
        for (int kf = 0; kf < 4; kf++) {
            uint32_t bf[8][2];
            #pragma unroll
            for (int p = 0; p < 4; p++) {
                uint32_t r4[4];
                ldsm_x4(r4, stgU + K_OFF + ((uint32_t)(p * 16) + bRowIdx) * AROW + kf * 32 + bColOff);
                bf[2*p][0] = r4[0]; bf[2*p][1] = r4[1];
                bf[2*p+1][0] = r4[2]; bf[2*p+1][1] = r4[3];
            }
            #pragma unroll
            for (int nf = 0; nf < 8; nf++) mma16816(sacc[nf], qh[kf], bf[nf]);
            #pragma unroll
            for (int nf = 0; nf < 8; nf++) mma16816(sacc[nf], ql[kf], bf[nf]);
        }

        // ---- online softmax ----
        float rm0 = sacc[0][0], rm1 = sacc[0][2];
        #pragma unroll
        for (int nf = 0; nf < 8; nf++) {
            rm0 = fmaxf(rm0, fmaxf(sacc[nf][0], sacc[nf][1]));
            rm1 = fmaxf(rm1, fmaxf(sacc[nf][2], sacc[nf][3]));
        }
        rm0 = fmaxf(rm0, __shfl_xor_sync(0xffffffffu, rm0, 1));
        rm0 = fmaxf(rm0, __shfl_xor_sync(0xffffffffu, rm0, 2));
        rm1 = fmaxf(rm1, __shfl_xor_sync(0xffffffffu, rm1, 1));
        rm1 = fmaxf(rm1, __shfl_xor_sync(0xffffffffu, rm1, 2));

        float mn0 = fmaxf(m0, rm0), mn1 = fmaxf(m1, rm1);
        float al0 = __expf(m0 - mn0), al1 = __expf(m1 - mn1);
        m0 = mn0; m1 = mn1;

        float ls0 = 0.f, ls1 = 0.f;
        #pragma unroll
        for (int nf = 0; nf < 8; nf++) {
            sacc[nf][0] = __expf(sacc[nf][0] - m0);
            sacc[nf][1] = __expf(sacc[nf][1] - m0);
            sacc[nf][2] = __expf(sacc[nf][2] - m1);
            sacc[nf][3] = __expf(sacc[nf][3] - m1);
            ls0 += sacc[nf][0] + sacc[nf][1];
            ls1 += sacc[nf][2] + sacc[nf][3];
        }
        ls0 += __shfl_xor_sync(0xffffffffu, ls0, 1);
        ls0 += __shfl_xor_sync(0xffffffffu, ls0, 2);
        ls1 += __shfl_xor_sync(0xffffffffu, ls1, 1);
        ls1 += __shfl_xor_sync(0xffffffffu, ls1, 2);
        l0 = l0 * al0 + ls0;
        l1 = l1 * al1 + ls1;

        #pragma unroll
        for (int nf = 0; nf < 8; nf++) {
            oacc[nf][0] *= al0; oacc[nf][1] *= al0;
            oacc[nf][2] *= al1; oacc[nf][3] *= al1;
        }

        // pack P fragments (bf16)
        uint32_t pa[4][4];
        #pragma unroll
        for (int k2 = 0; k2 < 4; k2++) {
            pa[k2][0] = pack_bf16(sacc[2*k2][0],   sacc[2*k2][1]);
            pa[k2][1] = pack_bf16(sacc[2*k2][2],   sacc[2*k2][3]);
            pa[k2][2] = pack_bf16(sacc[2*k2+1][0], sacc[2*k2+1][1]);
            pa[k2][3] = pack_bf16(sacc[2*k2+1][2], sacc[2*k2+1][3]);
        }

        // ---- O += P V (V hi + lo passes) ----
        #pragma unroll
        for (int k2 = 0; k2 < 4; k2++) {
            uint32_t vrow = (uint32_t)(k2 * 16 + ((lane >> 3) & 1) * 8 + (lane & 7));
            uint32_t lhalf = (uint32_t)(((lane >> 4) & 1) * 16);
            #pragma unroll
            for (int np = 0; np < 4; np++) {
                uint32_t addr = stgU + vrow * AROW + np * 32 + lhalf;
                uint32_t rh[4], rl[4];
                ldsm_x4_t(rh, addr + VH_OFF);
                mma16816(oacc[2*np],   pa[k2], rh + 0);
                mma16816(oacc[2*np+1], pa[k2], rh + 2);
                ldsm_x4_t(rl, addr + VL_OFF);
                mma16816(oacc[2*np],   pa[k2], rl + 0);
                mma16816(oacc[2*np+1], pa[k2], rl + 2);
            }
        }
        __syncthreads();
    }

    // ---- epilogue: O/l -> smem -> split bf16 y (coalesced) ----
    float* Osm = (float*)smem;
    const float inv0 = 1.f / l0, inv1 = 1.f / l1;
    #pragma unroll
    for (int nf = 0; nf < 8; nf++) {
        int c = nf * 8 + t * 2;
        Osm[(w * 16 + g)     * 72 + c]     = oacc[nf][0] * inv0;
        Osm[(w * 16 + g)     * 72 + c + 1] = oacc[nf][1] * inv0;
        Osm[(w * 16 + 8 + g) * 72 + c]     = oacc[nf][2] * inv1;
        Osm[(w * 16 + 8 + g) * 72 + c + 1] = oacc[nf][3] * inv1;
    }
    __syncthreads();

    {
        int r = tid >> 1, half = tid & 1;
        int b_ = bh >> 4, h = bh & 15;
        size_t base = ((size_t)b_ * Tt + q0 + r) * Cc + h * 64 + half * 32;
        uint16_t hb[32], lb[32];
        #pragma unroll
        for (int i = 0; i < 32; i++)
            split_one(Osm[r * 72 + half * 32 + i], hb[i], lb[i]);
        #pragma unroll
        for (int c4 = 0; c4 < 4; c4++) {
            *(uint4*)(g_yhi + base + c4 * 8) = *(uint4*)(hb + c4 * 8);
            *(uint4*)(g_ylo + base + c4 * 8) = *(uint4*)(lb + c4 * 8);
        }
    }
}

// ---------------------------------------------------------------------------
extern "C" void kernel_launch(void* const* d_in, const int* in_sizes, int n_in,
                              void* d_out, int out_size)
{
    const float* x      = (const float*)d_in[0];
    const float* W_attn = (const float*)d_in[1];
    const float* b_attn = (const float*)d_in[2];
    const float* W_proj = (const float*)d_in[3];
    const float* b_proj = (const float*)d_in[4];
    float* out = (float*)d_out;

    cudaFuncSetAttribute(mma_gemm_kernel<0>, cudaFuncAttributeMaxDynamicSharedMemorySize, GEMM_SMEM);
    cudaFuncSetAttribute(mma_gemm_kernel<1>, cudaFuncAttributeMaxDynamicSharedMemorySize, GEMM_SMEM);
    cudaFuncSetAttribute(attn_mma_kernel, cudaFuncAttributeMaxDynamicSharedMemorySize, ATT_SMEM);

    split_kernel<<<4096, 256>>>(x);
    transpose_split_kernel<0, NQKV><<<dim3(NQKV / 32, Kdim / 32), dim3(32, 8)>>>(W_attn);
    transpose_split_kernel<1, Cc><<<dim3(Cc / 32, Kdim / 32), dim3(32, 8)>>>(W_proj);

    mma_gemm_kernel<0><<<dim3(NQKV / 128, Mrows / 128), 256, GEMM_SMEM>>>(b_attn, nullptr);

    attn_mma_kernel<<<dim3(Tt / 128, Bb * Hh), 256, ATT_SMEM>>>();

    mma_gemm_kernel<1><<<dim3(Cc / 128, Mrows / 128), 256, GEMM_SMEM>>>(b_proj, out);
}

// round 7
// speedup vs baseline: 6.7047x; 1.4528x over previous
#include <cuda_runtime.h>
#include <cuda_fp16.h>
#include <cstdint>

#define Bb 4
#define Tt 2048
#define Cc 1024
#define Hh 16
#define Dd 64
#define Kdim 1024
#define NQKV 3072
#define Mrows 8192

// ---------------------------------------------------------------------------
// scratch (__device__ globals; allocation-free). All fp16 (stored as u16).
// ---------------------------------------------------------------------------
__device__ uint16_t g_xhi[(size_t)Mrows*Kdim];
__device__ uint16_t g_xlo[(size_t)Mrows*Kdim];
__device__ uint16_t g_yhi[(size_t)Mrows*Kdim];
__device__ uint16_t g_ylo[(size_t)Mrows*Kdim];
__device__ uint16_t g_wta[(size_t)NQKV*Kdim];     // W_attn^T single fp16
__device__ uint16_t g_wtp[(size_t)Cc*Kdim];       // W_proj^T single fp16

// attention operands, [b,h,t,d] fp16 (q pre-scaled by 1/8)
__device__ uint16_t g_qq[(size_t)Bb*Hh*Tt*Dd];
__device__ uint16_t g_kk[(size_t)Bb*Hh*Tt*Dd];
__device__ uint16_t g_vv[(size_t)Bb*Hh*Tt*Dd];

// ---------------------------------------------------------------------------
// helpers
// ---------------------------------------------------------------------------
__device__ __forceinline__ uint32_t smem_u32(const void* p) {
    uint32_t a;
    asm("{ .reg .u64 t; cvta.to.shared.u64 t, %1; cvt.u32.u64 %0, t; }" : "=r"(a) : "l"(p));
    return a;
}
__device__ __forceinline__ void cp16(uint32_t dst, const void* src) {
    asm volatile("cp.async.cg.shared.global [%0], [%1], 16;" :: "r"(dst), "l"(src));
}
#define CP_COMMIT() asm volatile("cp.async.commit_group;" ::: "memory")
#define CP_WAIT(n)  asm volatile("cp.async.wait_group %0;" :: "n"(n) : "memory")

__device__ __forceinline__ void mma16816(float d[4], const uint32_t a[4], const uint32_t b[2]) {
    asm volatile(
        "mma.sync.aligned.m16n8k16.row.col.f32.f16.f16.f32 "
        "{%0,%1,%2,%3}, {%4,%5,%6,%7}, {%8,%9}, {%0,%1,%2,%3};"
        : "+f"(d[0]), "+f"(d[1]), "+f"(d[2]), "+f"(d[3])
        : "r"(a[0]), "r"(a[1]), "r"(a[2]), "r"(a[3]), "r"(b[0]), "r"(b[1]));
}
__device__ __forceinline__ void ldsm_x4(uint32_t r[4], uint32_t a) {
    asm volatile("ldmatrix.sync.aligned.m8n8.x4.shared.b16 {%0,%1,%2,%3}, [%4];"
        : "=r"(r[0]), "=r"(r[1]), "=r"(r[2]), "=r"(r[3]) : "r"(a));
}
__device__ __forceinline__ void ldsm_x4_t(uint32_t r[4], uint32_t a) {
    asm volatile("ldmatrix.sync.aligned.m8n8.x4.trans.shared.b16 {%0,%1,%2,%3}, [%4];"
        : "=r"(r[0]), "=r"(r[1]), "=r"(r[2]), "=r"(r[3]) : "r"(a));
}

__device__ __forceinline__ void split_one_h(float v, uint16_t& h, uint16_t& l) {
    __half hb = __float2half_rn(v);
    float rem = v - __half2float(hb);
    __half lb = __float2half_rn(rem);
    h = *reinterpret_cast<uint16_t*>(&hb);
    l = *reinterpret_cast<uint16_t*>(&lb);
}
__device__ __forceinline__ uint16_t to_h(float v) {
    __half hb = __float2half_rn(v);
    return *reinterpret_cast<uint16_t*>(&hb);
}
__device__ __forceinline__ uint32_t pack_h2(float a, float b) {
    __half2 h2 = __floats2half2_rn(a, b);
    return *reinterpret_cast<uint32_t*>(&h2);
}

// ---------------------------------------------------------------------------
// prep kernels
// ---------------------------------------------------------------------------
__global__ void split_kernel(const float* __restrict__ src) {
    size_t n = (size_t)Mrows * Kdim;
    for (size_t i = blockIdx.x * (size_t)blockDim.x + threadIdx.x; i < n;
         i += (size_t)gridDim.x * blockDim.x)
        split_one_h(src[i], g_xhi[i], g_xlo[i]);
}

// transpose: W[Kdim][N] -> Wt[N][Kdim] single fp16
template<int WHICH, int N>
__global__ void transpose_kernel(const float* __restrict__ W) {
    uint16_t* dst = (WHICH == 0) ? g_wta : g_wtp;
    __shared__ float t[32][33];
    int n0 = blockIdx.x * 32, k0 = blockIdx.y * 32;
    #pragma unroll
    for (int i = 0; i < 4; i++)
        t[threadIdx.y + 8 * i][threadIdx.x] = W[(size_t)(k0 + threadIdx.y + 8 * i) * N + n0 + threadIdx.x];
    __syncthreads();
    #pragma unroll
    for (int i = 0; i < 4; i++) {
        int n = n0 + threadIdx.y + 8 * i;
        int k = k0 + threadIdx.x;
        dst[(size_t)n * Kdim + k] = to_h(t[threadIdx.x][threadIdx.y + 8 * i]);
    }
}

// ---------------------------------------------------------------------------
// mma.sync fp16 GEMM (2-pass A split, B single), 128x128 block, BK=32,
// 8 warps (4Mx2N), 3-stage cp.async pipeline, 2 CTA/SM, ldmatrix loads.
// ROWB=80: 16B-aligned + conflict-free LDSM (banks 20r mod 32 distinct).
// MODE 0: A=x(split), B=W_attn^T -> scatter q/k/v fp16
// MODE 1: A=y(split), B=W_proj^T -> fp32 out
// ---------------------------------------------------------------------------
#define BK 32
#define NSTG (Kdim / BK)           // 32
#define ROWB 80
#define MAT_B (128 * ROWB)         // 10240
#define STAGE_B (3 * MAT_B)        // 30720 (Ahi, Alo, B)
#define GEMM_SMEM (3 * STAGE_B)    // 92160

__device__ __forceinline__ void preload_stage(uint32_t st,
        const uint16_t* __restrict__ Ahi, const uint16_t* __restrict__ Alo,
        const uint16_t* __restrict__ Bs,
        int row0, int col0, int kc, int tid)
{
    #pragma unroll
    for (int i = 0; i < 2; i++) {
        int idx = tid + i * 256;
        int r = idx >> 2;
        int c = idx & 3;
        uint32_t off = (uint32_t)(r * ROWB + c * 16);
        size_t gA = (size_t)(row0 + r) * Kdim + kc + c * 8;
        size_t gB = (size_t)(col0 + r) * Kdim + kc + c * 8;
        cp16(st + 0 * MAT_B + off, Ahi + gA);
        cp16(st + 1 * MAT_B + off, Alo + gA);
        cp16(st + 2 * MAT_B + off, Bs + gB);
    }
}

template<int MODE>
__global__ void __launch_bounds__(256, 2) mma_gemm_kernel(const float* __restrict__ bias,
                                                          float* __restrict__ out)
{
    extern __shared__ char smem[];
    const uint32_t sb = smem_u32(smem);
    const int tid  = threadIdx.x;
    const int wid  = tid >> 5;
    const int lane = tid & 31;
    const int g = lane >> 2;
    const int t = lane & 3;
    const int warpM = wid & 3;
    const int warpN = wid >> 2;
    const int row0 = blockIdx.y * 128;
    const int col0 = blockIdx.x * 128;

    const uint16_t* Ahi = (MODE == 0) ? g_xhi : g_yhi;
    const uint16_t* Alo = (MODE == 0) ? g_xlo : g_ylo;
    const uint16_t* Bs  = (MODE == 0) ? g_wta : g_wtp;

    float acc[2][8][4];
    #pragma unroll
    for (int mt = 0; mt < 2; mt++)
        #pragma unroll
        for (int nt = 0; nt < 8; nt++)
            #pragma unroll
            for (int j = 0; j < 4; j++) acc[mt][nt][j] = 0.f;

    const uint32_t aRowIdx = (uint32_t)(((lane >> 3) & 1) * 8 + (lane & 7));
    const uint32_t aColOff = (uint32_t)(((lane >> 4) & 1) * 16);
    const uint32_t bRowIdx = (uint32_t)(((lane >> 4) & 1) * 8 + (lane & 7));
    const uint32_t bColOff = (uint32_t)(((lane >> 3) & 1) * 16);

    // prologue: 2 stages in flight
    preload_stage(sb + 0 * STAGE_B, Ahi, Alo, Bs, row0, col0, 0 * BK, tid); CP_COMMIT();
    preload_stage(sb + 1 * STAGE_B, Ahi, Alo, Bs, row0, col0, 1 * BK, tid); CP_COMMIT();

    for (int s = 0; s < NSTG; s++) {
        if (s + 1 < NSTG) { CP_WAIT(1); } else { CP_WAIT(0); }
        __syncthreads();
        // preload s+2 into slot (s+2)%3 == (s-1)%3: all threads are past
        // compute(s-1) (they passed the sync above), so the slot is free.
        if (s + 2 < NSTG) {
            preload_stage(sb + (uint32_t)(((s + 2) % 3) * STAGE_B),
                          Ahi, Alo, Bs, row0, col0, (s + 2) * BK, tid);
            CP_COMMIT();
        }

        const uint32_t stg = sb + (uint32_t)((s % 3) * STAGE_B);
        const uint32_t Ah = stg + 0 * MAT_B;
        const uint32_t Al = stg + 1 * MAT_B;
        const uint32_t Bm = stg + 2 * MAT_B;

        #pragma unroll
        for (int ks = 0; ks < 2; ks++) {
            const uint32_t kByte = (uint32_t)(ks * 32);
            uint32_t ah[2][4], al[2][4];
            #pragma unroll
            for (int mt = 0; mt < 2; mt++) {
                uint32_t ra = (uint32_t)(warpM * 32 + mt * 16) + aRowIdx;
                ldsm_x4(ah[mt], Ah + ra * ROWB + kByte + aColOff);
                ldsm_x4(al[mt], Al + ra * ROWB + kByte + aColOff);
            }
            #pragma unroll
            for (int ntp = 0; ntp < 4; ntp++) {
                uint32_t rb = (uint32_t)(warpN * 64 + ntp * 16) + bRowIdx;
                uint32_t bb[4];
                ldsm_x4(bb, Bm + rb * ROWB + kByte + bColOff);
                #pragma unroll
                for (int half = 0; half < 2; half++) {
                    #pragma unroll
                    for (int mt = 0; mt < 2; mt++) {
                        mma16816(acc[mt][ntp * 2 + half], ah[mt], bb + half * 2);
                        mma16816(acc[mt][ntp * 2 + half], al[mt], bb + half * 2);
                    }
                }
            }
        }
    }

    #pragma unroll
    for (int mt = 0; mt < 2; mt++) {
        #pragma unroll
        for (int nt = 0; nt < 8; nt++) {
            #pragma unroll
            for (int half = 0; half < 2; half++) {
                int m = row0 + warpM * 32 + mt * 16 + g + half * 8;
                int n = col0 + warpN * 64 + nt * 8 + t * 2;
                float v0 = acc[mt][nt][half * 2 + 0] + bias[n];
                float v1 = acc[mt][nt][half * 2 + 1] + bias[n + 1];
                if (MODE == 0) {
                    int b_ = m >> 11;
                    int tt = m & 2047;
                    int which = n >> 10;
                    int cc = n & 1023;
                    int h = cc >> 6;
                    int d = cc & 63;
                    size_t base = (((size_t)b_ * Hh + h) * Tt + tt) * Dd + d;
                    if (which == 0) {
                        *(uint32_t*)&g_qq[base] = pack_h2(v0 * 0.125f, v1 * 0.125f);
                    } else if (which == 1) {
                        *(uint32_t*)&g_kk[base] = pack_h2(v0, v1);
                    } else {
                        *(uint32_t*)&g_vv[base] = pack_h2(v0, v1);
                    }
                } else {
                    float* p = out + (size_t)m * Cc + n;
                    p[0] = v0; p[1] = v1;
                }
            }
        }
    }
}

// ---------------------------------------------------------------------------
// Flash attention via mma.sync fp16 (single-pass S and PV)
// grid (Tt/128, Bb*Hh), 256 threads = 8 warps, warp = 16 q-rows x all keys.
// K-tile = 64 keys; stage = K + V (2 matrices). AROW=144 (16-aligned).
// ---------------------------------------------------------------------------
#define TK 64
#define NTILE (Tt / TK)             // 32
#define AROW 144
#define VOFF (64 * AROW)            // V inside stage
#define STG_B (128 * AROW)          // 18432
#define ATT_SMEM (2 * STG_B)        // 36864

__global__ void __launch_bounds__(256, 2) attn_mma_kernel()
{
    extern __shared__ char smem[];
    const uint32_t sb = smem_u32(smem);
    const int tid  = threadIdx.x;
    const int w    = tid >> 5;
    const int lane = tid & 31;
    const int g = lane >> 2;
    const int t = lane & 3;
    const int q0 = blockIdx.x * 128;
    const int bh = blockIdx.y;

    const size_t seqBase = (size_t)bh * Tt * Dd;

    const uint32_t aRowIdx = (uint32_t)(((lane >> 3) & 1) * 8 + (lane & 7));
    const uint32_t aColOff = (uint32_t)(((lane >> 4) & 1) * 16);
    const uint32_t bRowIdx = (uint32_t)(((lane >> 4) & 1) * 8 + (lane & 7));
    const uint32_t bColOff = (uint32_t)(((lane >> 3) & 1) * 16);

    // ---- prologue: Q tile -> smem -> fragments ----
    #pragma unroll
    for (int j = 0; j < 4; j++) {
        int idx = tid + j * 256;
        int r = idx >> 3, c = idx & 7;
        size_t gsrc = seqBase + (size_t)(q0 + r) * Dd + c * 8;
        *(uint4*)(smem + r * AROW + c * 16) = *(const uint4*)(g_qq + gsrc);
    }
    __syncthreads();

    uint32_t qh[4][4];
    {
        uint32_t qrow = (uint32_t)(w * 16) + aRowIdx;
        #pragma unroll
        for (int kf = 0; kf < 4; kf++)
            ldsm_x4(qh[kf], sb + qrow * AROW + kf * 32 + aColOff);
    }
    __syncthreads();

    float oacc[8][4];
    #pragma unroll
    for (int nf = 0; nf < 8; nf++)
        #pragma unroll
        for (int j = 0; j < 4; j++) oacc[nf][j] = 0.f;
    float m0 = -1e30f, m1 = -1e30f, l0 = 0.f, l1 = 0.f;

    // stage 0
    #pragma unroll
    for (int j = 0; j < 2; j++) {
        int idx = tid + j * 256;
        int r = idx >> 3, c = idx & 7;
        uint32_t off = (uint32_t)(r * AROW + c * 16);
        size_t gsrc = seqBase + (size_t)r * Dd + c * 8;
        cp16(sb + off,        g_kk + gsrc);
        cp16(sb + VOFF + off, g_vv + gsrc);
    }
    CP_COMMIT();

    for (int kt = 0; kt < NTILE; kt++) {
        CP_WAIT(0);
        __syncthreads();
        if (kt + 1 < NTILE) {
            uint32_t st = sb + ((kt + 1) & 1) * STG_B;
            #pragma unroll
            for (int j = 0; j < 2; j++) {
                int idx = tid + j * 256;
                int r = idx >> 3, c = idx & 7;
                uint32_t off = (uint32_t)(r * AROW + c * 16);
                size_t gsrc = seqBase + (size_t)((kt + 1) * TK + r) * Dd + c * 8;
                cp16(st + off,        g_kk + gsrc);
                cp16(st + VOFF + off, g_vv + gsrc);
            }
            CP_COMMIT();
        }

        const uint32_t stgU = sb + (kt & 1) * STG_B;

        // ---- S = Q K^T (single pass) ----
        float sacc[8][4];
        #pragma unroll
        for (int nf = 0; nf < 8; nf++)
            #pragma unroll
            for (int j = 0; j < 4; j++) sacc[nf][j] = 0.f;

        #pragma unroll
        for (int kf = 0; kf < 4; kf++) {
            uint32_t bf[8][2];
            #pragma unroll
            for (int p = 0; p < 4; p++) {
                uint32_t r4[4];
                ldsm_x4(r4, stgU + ((uint32_t)(p * 16) + bRowIdx) * AROW + kf * 32 + bColOff);
                bf[2*p][0] = r4[0]; bf[2*p][1] = r4[1];
                bf[2*p+1][0] = r4[2]; bf[2*p+1][1] = r4[3];
            }
            #pragma unroll
            for (int nf = 0; nf < 8; nf++) mma16816(sacc[nf], qh[kf], bf[nf]);
        }

        // ---- online softmax ----
        float rm0 = sacc[0][0], rm1 = sacc[0][2];
        #pragma unroll
        for (int nf = 0; nf < 8; nf++) {
            rm0 = fmaxf(rm0, fmaxf(sacc[nf][0], sacc[nf][1]));
            rm1 = fmaxf(rm1, fmaxf(sacc[nf][2], sacc[nf][3]));
        }
        rm0 = fmaxf(rm0, __shfl_xor_sync(0xffffffffu, rm0, 1));
        rm0 = fmaxf(rm0, __shfl_xor_sync(0xffffffffu, rm0, 2));
        rm1 = fmaxf(rm1, __shfl_xor_sync(0xffffffffu, rm1, 1));
        rm1 = fmaxf(rm1, __shfl_xor_sync(0xffffffffu, rm1, 2));

        float mn0 = fmaxf(m0, rm0), mn1 = fmaxf(m1, rm1);
        float al0 = __expf(m0 - mn0), al1 = __expf(m1 - mn1);
        m0 = mn0; m1 = mn1;

        float ls0 = 0.f, ls1 = 0.f;
        #pragma unroll
        for (int nf = 0; nf < 8; nf++) {
            sacc[nf][0] = __expf(sacc[nf][0] - m0);
            sacc[nf][1] = __expf(sacc[nf][1] - m0);
            sacc[nf][2] = __expf(sacc[nf][2] - m1);
            sacc[nf][3] = __expf(sacc[nf][3] - m1);
            ls0 += sacc[nf][0] + sacc[nf][1];
            ls1 += sacc[nf][2] + sacc[nf][3];
        }
        ls0 += __shfl_xor_sync(0xffffffffu, ls0, 1);
        ls0 += __shfl_xor_sync(0xffffffffu, ls0, 2);
        ls1 += __shfl_xor_sync(0xffffffffu, ls1, 1);
        ls1 += __shfl_xor_sync(0xffffffffu, ls1, 2);
        l0 = l0 * al0 + ls0;
        l1 = l1 * al1 + ls1;

        #pragma unroll
        for (int nf = 0; nf < 8; nf++) {
            oacc[nf][0] *= al0; oacc[nf][1] *= al0;
            oacc[nf][2] *= al1; oacc[nf][3] *= al1;
        }

        // pack P fragments (fp16)
        uint32_t pa[4][4];
        #pragma unroll
        for (int k2 = 0; k2 < 4; k2++) {
            pa[k2][0] = pack_h2(sacc[2*k2][0],   sacc[2*k2][1]);
            pa[k2][1] = pack_h2(sacc[2*k2][2],   sacc[2*k2][3]);
            pa[k2][2] = pack_h2(sacc[2*k2+1][0], sacc[2*k2+1][1]);
            pa[k2][3] = pack_h2(sacc[2*k2+1][2], sacc[2*k2+1][3]);
        }

        // ---- O += P V (single pass) ----
        #pragma unroll
        for (int k2 = 0; k2 < 4; k2++) {
            uint32_t vrow = (uint32_t)(k2 * 16 + ((lane >> 3) & 1) * 8 + (lane & 7));
            uint32_t lhalf = (uint32_t)(((lane >> 4) & 1) * 16);
            #pragma unroll
            for (int np = 0; np < 4; np++) {
                uint32_t rh[4];
                ldsm_x4_t(rh, stgU + VOFF + vrow * AROW + np * 32 + lhalf);
                mma16816(oacc[2*np],   pa[k2], rh + 0);
                mma16816(oacc[2*np+1], pa[k2], rh + 2);
            }
        }
    }

    // ---- epilogue: O/l -> smem -> split fp16 y ----
    __syncthreads();
    float* Osm = (float*)smem;
    const float inv0 = 1.f / l0, inv1 = 1.f / l1;
    #pragma unroll
    for (int nf = 0; nf < 8; nf++) {
        int c = nf * 8 + t * 2;
        Osm[(w * 16 + g)     * 72 + c]     = oacc[nf][0] * inv0;
        Osm[(w * 16 + g)     * 72 + c + 1] = oacc[nf][1] * inv0;
        Osm[(w * 16 + 8 + g) * 72 + c]     = oacc[nf][2] * inv1;
        Osm[(w * 16 + 8 + g) * 72 + c + 1] = oacc[nf][3] * inv1;
    }
    __syncthreads();

    {
        int r = tid >> 1, half = tid & 1;
        int b_ = bh >> 4, h = bh & 15;
        size_t base = ((size_t)b_ * Tt + q0 + r) * Cc + h * 64 + half * 32;
        uint16_t hb[32], lb[32];
        #pragma unroll
        for (int i = 0; i < 32; i++)
            split_one_h(Osm[r * 72 + half * 32 + i], hb[i], lb[i]);
        #pragma unroll
        for (int c4 = 0; c4 < 4; c4++) {
            *(uint4*)(g_yhi + base + c4 * 8) = *(uint4*)(hb + c4 * 8);
            *(uint4*)(g_ylo + base + c4 * 8) = *(uint4*)(lb + c4 * 8);
        }
    }
}

// ---------------------------------------------------------------------------
extern "C" void kernel_launch(void* const* d_in, const int* in_sizes, int n_in,
                              void* d_out, int out_size)
{
    const float* x      = (const float*)d_in[0];
    const float* W_attn = (const float*)d_in[1];
    const float* b_attn = (const float*)d_in[2];
    const float* W_proj = (const float*)d_in[3];
    const float* b_proj = (const float*)d_in[4];
    float* out = (float*)d_out;

    cudaFuncSetAttribute(mma_gemm_kernel<0>, cudaFuncAttributeMaxDynamicSharedMemorySize, GEMM_SMEM);
    cudaFuncSetAttribute(mma_gemm_kernel<1>, cudaFuncAttributeMaxDynamicSharedMemorySize, GEMM_SMEM);
    cudaFuncSetAttribute(attn_mma_kernel, cudaFuncAttributeMaxDynamicSharedMemorySize, ATT_SMEM);

    split_kernel<<<4096, 256>>>(x);
    transpose_kernel<0, NQKV><<<dim3(NQKV / 32, Kdim / 32), dim3(32, 8)>>>(W_attn);
    transpose_kernel<1, Cc><<<dim3(Cc / 32, Kdim / 32), dim3(32, 8)>>>(W_proj);

    mma_gemm_kernel<0><<<dim3(NQKV / 128, Mrows / 128), 256, GEMM_SMEM>>>(b_attn, nullptr);

    attn_mma_kernel<<<dim3(Tt / 128, Bb * Hh), 256, ATT_SMEM>>>();

    mma_gemm_kernel<1><<<dim3(Cc / 128, Mrows / 128), 256, GEMM_SMEM>>>(b_proj, out);
}

// round 8
// speedup vs baseline: 9.2685x; 1.3824x over previous
#include <cuda_runtime.h>
#include <cuda_fp16.h>
#include <cstdint>

#define Bb 4
#define Tt 2048
#define Cc 1024
#define Hh 16
#define Dd 64
#define Kdim 1024
#define NQKV 3072
#define Mrows 8192

// ---------------------------------------------------------------------------
// scratch (__device__ globals; allocation-free). All fp16 (stored as u16).
// ---------------------------------------------------------------------------
__device__ uint16_t g_xx[(size_t)Mrows*Kdim];      // x fp16
__device__ uint16_t g_yy[(size_t)Mrows*Kdim];      // attention output fp16
__device__ uint16_t g_wta[(size_t)NQKV*Kdim];      // W_attn^T fp16
__device__ uint16_t g_wtp[(size_t)Cc*Kdim];        // W_proj^T fp16

// attention operands, [b,h,t,d] fp16 (q pre-scaled by 1/8)
__device__ uint16_t g_qq[(size_t)Bb*Hh*Tt*Dd];
__device__ uint16_t g_kk[(size_t)Bb*Hh*Tt*Dd];
__device__ uint16_t g_vv[(size_t)Bb*Hh*Tt*Dd];

// ---------------------------------------------------------------------------
// helpers
// ---------------------------------------------------------------------------
__device__ __forceinline__ uint32_t smem_u32(const void* p) {
    uint32_t a;
    asm("{ .reg .u64 t; cvta.to.shared.u64 t, %1; cvt.u32.u64 %0, t; }" : "=r"(a) : "l"(p));
    return a;
}
__device__ __forceinline__ void cp16(uint32_t dst, const void* src) {
    asm volatile("cp.async.cg.shared.global [%0], [%1], 16;" :: "r"(dst), "l"(src));
}
#define CP_COMMIT() asm volatile("cp.async.commit_group;" ::: "memory")
#define CP_WAIT(n)  asm volatile("cp.async.wait_group %0;" :: "n"(n) : "memory")

__device__ __forceinline__ void mma16816(float d[4], const uint32_t a[4], const uint32_t b[2]) {
    asm volatile(
        "mma.sync.aligned.m16n8k16.row.col.f32.f16.f16.f32 "
        "{%0,%1,%2,%3}, {%4,%5,%6,%7}, {%8,%9}, {%0,%1,%2,%3};"
        : "+f"(d[0]), "+f"(d[1]), "+f"(d[2]), "+f"(d[3])
        : "r"(a[0]), "r"(a[1]), "r"(a[2]), "r"(a[3]), "r"(b[0]), "r"(b[1]));
}
__device__ __forceinline__ void ldsm_x4(uint32_t r[4], uint32_t a) {
    asm volatile("ldmatrix.sync.aligned.m8n8.x4.shared.b16 {%0,%1,%2,%3}, [%4];"
        : "=r"(r[0]), "=r"(r[1]), "=r"(r[2]), "=r"(r[3]) : "r"(a));
}
__device__ __forceinline__ void ldsm_x4_t(uint32_t r[4], uint32_t a) {
    asm volatile("ldmatrix.sync.aligned.m8n8.x4.trans.shared.b16 {%0,%1,%2,%3}, [%4];"
        : "=r"(r[0]), "=r"(r[1]), "=r"(r[2]), "=r"(r[3]) : "r"(a));
}

__device__ __forceinline__ uint16_t to_h(float v) {
    __half hb = __float2half_rn(v);
    return *reinterpret_cast<uint16_t*>(&hb);
}
__device__ __forceinline__ uint32_t pack_h2(float a, float b) {
    __half2 h2 = __floats2half2_rn(a, b);
    return *reinterpret_cast<uint32_t*>(&h2);
}

// ---------------------------------------------------------------------------
// prep kernels
// ---------------------------------------------------------------------------
__global__ void convert_kernel(const float* __restrict__ src) {
    size_t n = (size_t)Mrows * Kdim;
    for (size_t i = (blockIdx.x * (size_t)blockDim.x + threadIdx.x) * 4; i < n;
         i += (size_t)gridDim.x * blockDim.x * 4) {
        float4 v = *(const float4*)(src + i);
        uint32_t p0 = pack_h2(v.x, v.y);
        uint32_t p1 = pack_h2(v.z, v.w);
        *(uint2*)&g_xx[i] = make_uint2(p0, p1);
    }
}

// transpose: W[Kdim][N] -> Wt[N][Kdim] fp16
template<int WHICH, int N>
__global__ void transpose_kernel(const float* __restrict__ W) {
    uint16_t* dst = (WHICH == 0) ? g_wta : g_wtp;
    __shared__ float t[32][33];
    int n0 = blockIdx.x * 32, k0 = blockIdx.y * 32;
    #pragma unroll
    for (int i = 0; i < 4; i++)
        t[threadIdx.y + 8 * i][threadIdx.x] = W[(size_t)(k0 + threadIdx.y + 8 * i) * N + n0 + threadIdx.x];
    __syncthreads();
    #pragma unroll
    for (int i = 0; i < 4; i++) {
        int n = n0 + threadIdx.y + 8 * i;
        int k = k0 + threadIdx.x;
        dst[(size_t)n * Kdim + k] = to_h(t[threadIdx.x][threadIdx.y + 8 * i]);
    }
}

// ---------------------------------------------------------------------------
// mma.sync fp16 GEMM (single pass), 128x128 block, BK=32, 8 warps (4Mx2N),
// 3-stage cp.async pipeline, ldmatrix loads.
// ROWB=80: 16B-aligned + conflict-free LDSM (banks 20r mod 32 distinct).
// MODE 0: A=g_xx, B=W_attn^T -> scatter q/k/v fp16
// MODE 1: A=g_yy, B=W_proj^T -> fp32 out
// ---------------------------------------------------------------------------
#define BK 32
#define NSTG (Kdim / BK)           // 32
#define ROWB 80
#define MAT_B (128 * ROWB)         // 10240
#define STAGE_B (2 * MAT_B)        // 20480 (A, B)
#define GEMM_SMEM (3 * STAGE_B)    // 61440

__device__ __forceinline__ void preload_stage(uint32_t st,
        const uint16_t* __restrict__ As, const uint16_t* __restrict__ Bs,
        int row0, int col0, int kc, int tid)
{
    #pragma unroll
    for (int i = 0; i < 2; i++) {
        int idx = tid + i * 256;
        int r = idx >> 2;
        int c = idx & 3;
        uint32_t off = (uint32_t)(r * ROWB + c * 16);
        size_t gA = (size_t)(row0 + r) * Kdim + kc + c * 8;
        size_t gB = (size_t)(col0 + r) * Kdim + kc + c * 8;
        cp16(st + 0 * MAT_B + off, As + gA);
        cp16(st + 1 * MAT_B + off, Bs + gB);
    }
}

template<int MODE>
__global__ void __launch_bounds__(256, 2) mma_gemm_kernel(const float* __restrict__ bias,
                                                          float* __restrict__ out)
{
    extern __shared__ char smem[];
    const uint32_t sb = smem_u32(smem);
    const int tid  = threadIdx.x;
    const int wid  = tid >> 5;
    const int lane = tid & 31;
    const int g = lane >> 2;
    const int t = lane & 3;
    const int warpM = wid & 3;
    const int warpN = wid >> 2;
    const int row0 = blockIdx.y * 128;
    const int col0 = blockIdx.x * 128;

    const uint16_t* As = (MODE == 0) ? g_xx : g_yy;
    const uint16_t* Bs = (MODE == 0) ? g_wta : g_wtp;

    float acc[2][8][4];
    #pragma unroll
    for (int mt = 0; mt < 2; mt++)
        #pragma unroll
        for (int nt = 0; nt < 8; nt++)
            #pragma unroll
            for (int j = 0; j < 4; j++) acc[mt][nt][j] = 0.f;

    const uint32_t aRowIdx = (uint32_t)(((lane >> 3) & 1) * 8 + (lane & 7));
    const uint32_t aColOff = (uint32_t)(((lane >> 4) & 1) * 16);
    const uint32_t bRowIdx = (uint32_t)(((lane >> 4) & 1) * 8 + (lane & 7));
    const uint32_t bColOff = (uint32_t)(((lane >> 3) & 1) * 16);

    preload_stage(sb + 0 * STAGE_B, As, Bs, row0, col0, 0 * BK, tid); CP_COMMIT();
    preload_stage(sb + 1 * STAGE_B, As, Bs, row0, col0, 1 * BK, tid); CP_COMMIT();

    for (int s = 0; s < NSTG; s++) {
        if (s + 1 < NSTG) { CP_WAIT(1); } else { CP_WAIT(0); }
        __syncthreads();
        if (s + 2 < NSTG) {
            preload_stage(sb + (uint32_t)(((s + 2) % 3) * STAGE_B),
                          As, Bs, row0, col0, (s + 2) * BK, tid);
            CP_COMMIT();
        }

        const uint32_t stg = sb + (uint32_t)((s % 3) * STAGE_B);
        const uint32_t Am = stg + 0 * MAT_B;
        const uint32_t Bm = stg + 1 * MAT_B;

        #pragma unroll
        for (int ks = 0; ks < 2; ks++) {
            const uint32_t kByte = (uint32_t)(ks * 32);
            uint32_t ah[2][4];
            #pragma unroll
            for (int mt = 0; mt < 2; mt++) {
                uint32_t ra = (uint32_t)(warpM * 32 + mt * 16) + aRowIdx;
                ldsm_x4(ah[mt], Am + ra * ROWB + kByte + aColOff);
            }
            #pragma unroll
            for (int ntp = 0; ntp < 4; ntp++) {
                uint32_t rb = (uint32_t)(warpN * 64 + ntp * 16) + bRowIdx;
                uint32_t bb[4];
                ldsm_x4(bb, Bm + rb * ROWB + kByte + bColOff);
                #pragma unroll
                for (int half = 0; half < 2; half++)
                    #pragma unroll
                    for (int mt = 0; mt < 2; mt++)
                        mma16816(acc[mt][ntp * 2 + half], ah[mt], bb + half * 2);
            }
        }
    }

    #pragma unroll
    for (int mt = 0; mt < 2; mt++) {
        #pragma unroll
        for (int nt = 0; nt < 8; nt++) {
            #pragma unroll
            for (int half = 0; half < 2; half++) {
                int m = row0 + warpM * 32 + mt * 16 + g + half * 8;
                int n = col0 + warpN * 64 + nt * 8 + t * 2;
                float v0 = acc[mt][nt][half * 2 + 0] + bias[n];
                float v1 = acc[mt][nt][half * 2 + 1] + bias[n + 1];
                if (MODE == 0) {
                    int b_ = m >> 11;
                    int tt = m & 2047;
                    int which = n >> 10;
                    int cc = n & 1023;
                    int h = cc >> 6;
                    int d = cc & 63;
                    size_t base = (((size_t)b_ * Hh + h) * Tt + tt) * Dd + d;
                    if (which == 0) {
                        *(uint32_t*)&g_qq[base] = pack_h2(v0 * 0.125f, v1 * 0.125f);
                    } else if (which == 1) {
                        *(uint32_t*)&g_kk[base] = pack_h2(v0, v1);
                    } else {
                        *(uint32_t*)&g_vv[base] = pack_h2(v0, v1);
                    }
                } else {
                    float* p = out + (size_t)m * Cc + n;
                    p[0] = v0; p[1] = v1;
                }
            }
        }
    }
}

// ---------------------------------------------------------------------------
// Flash attention via mma.sync fp16 (single-pass S and PV)
// grid (Tt/128, Bb*Hh), 256 threads = 8 warps, warp = 16 q-rows x all keys.
// K-tile = 64 keys; stage = K + V. AROW=144 (16-aligned).
// ---------------------------------------------------------------------------
#define TK 64
#define NTILE (Tt / TK)             // 32
#define AROW 144
#define VOFF (64 * AROW)
#define STG_B (128 * AROW)          // 18432
#define ATT_SMEM (2 * STG_B)        // 36864

__global__ void __launch_bounds__(256, 2) attn_mma_kernel()
{
    extern __shared__ char smem[];
    const uint32_t sb = smem_u32(smem);
    const int tid  = threadIdx.x;
    const int w    = tid >> 5;
    const int lane = tid & 31;
    const int g = lane >> 2;
    const int t = lane & 3;
    const int q0 = blockIdx.x * 128;
    const int bh = blockIdx.y;

    const size_t seqBase = (size_t)bh * Tt * Dd;

    const uint32_t aRowIdx = (uint32_t)(((lane >> 3) & 1) * 8 + (lane & 7));
    const uint32_t aColOff = (uint32_t)(((lane >> 4) & 1) * 16);
    const uint32_t bRowIdx = (uint32_t)(((lane >> 4) & 1) * 8 + (lane & 7));
    const uint32_t bColOff = (uint32_t)(((lane >> 3) & 1) * 16);

    // ---- prologue: Q tile -> smem -> fragments ----
    #pragma unroll
    for (int j = 0; j < 4; j++) {
        int idx = tid + j * 256;
        int r = idx >> 3, c = idx & 7;
        size_t gsrc = seqBase + (size_t)(q0 + r) * Dd + c * 8;
        *(uint4*)(smem + r * AROW + c * 16) = *(const uint4*)(g_qq + gsrc);
    }
    __syncthreads();

    uint32_t qh[4][4];
    {
        uint32_t qrow = (uint32_t)(w * 16) + aRowIdx;
        #pragma unroll
        for (int kf = 0; kf < 4; kf++)
            ldsm_x4(qh[kf], sb + qrow * AROW + kf * 32 + aColOff);
    }
    __syncthreads();

    float oacc[8][4];
    #pragma unroll
    for (int nf = 0; nf < 8; nf++)
        #pragma unroll
        for (int j = 0; j < 4; j++) oacc[nf][j] = 0.f;
    float m0 = -1e30f, m1 = -1e30f, l0 = 0.f, l1 = 0.f;

    // stage 0
    #pragma unroll
    for (int j = 0; j < 2; j++) {
        int idx = tid + j * 256;
        int r = idx >> 3, c = idx & 7;
        uint32_t off = (uint32_t)(r * AROW + c * 16);
        size_t gsrc = seqBase + (size_t)r * Dd + c * 8;
        cp16(sb + off,        g_kk + gsrc);
        cp16(sb + VOFF + off, g_vv + gsrc);
    }
    CP_COMMIT();

    for (int kt = 0; kt < NTILE; kt++) {
        CP_WAIT(0);
        __syncthreads();
        if (kt + 1 < NTILE) {
            uint32_t st = sb + ((kt + 1) & 1) * STG_B;
            #pragma unroll
            for (int j = 0; j < 2; j++) {
                int idx = tid + j * 256;
                int r = idx >> 3, c = idx & 7;
                uint32_t off = (uint32_t)(r * AROW + c * 16);
                size_t gsrc = seqBase + (size_t)((kt + 1) * TK + r) * Dd + c * 8;
                cp16(st + off,        g_kk + gsrc);
                cp16(st + VOFF + off, g_vv + gsrc);
            }
            CP_COMMIT();
        }

        const uint32_t stgU = sb + (kt & 1) * STG_B;

        // ---- S = Q K^T ----
        float sacc[8][4];
        #pragma unroll
        for (int nf = 0; nf < 8; nf++)
            #pragma unroll
            for (int j = 0; j < 4; j++) sacc[nf][j] = 0.f;

        #pragma unroll
        for (int kf = 0; kf < 4; kf++) {
            uint32_t bf[8][2];
            #pragma unroll
            for (int p = 0; p < 4; p++) {
                uint32_t r4[4];
                ldsm_x4(r4, stgU + ((uint32_t)(p * 16) + bRowIdx) * AROW + kf * 32 + bColOff);
                bf[2*p][0] = r4[0]; bf[2*p][1] = r4[1];
                bf[2*p+1][0] = r4[2]; bf[2*p+1][1] = r4[3];
            }
            #pragma unroll
            for (int nf = 0; nf < 8; nf++) mma16816(sacc[nf], qh[kf], bf[nf]);
        }

        // ---- online softmax ----
        float rm0 = sacc[0][0], rm1 = sacc[0][2];
        #pragma unroll
        for (int nf = 0; nf < 8; nf++) {
            rm0 = fmaxf(rm0, fmaxf(sacc[nf][0], sacc[nf][1]));
            rm1 = fmaxf(rm1, fmaxf(sacc[nf][2], sacc[nf][3]));
        }
        rm0 = fmaxf(rm0, __shfl_xor_sync(0xffffffffu, rm0, 1));
        rm0 = fmaxf(rm0, __shfl_xor_sync(0xffffffffu, rm0, 2));
        rm1 = fmaxf(rm1, __shfl_xor_sync(0xffffffffu, rm1, 1));
        rm1 = fmaxf(rm1, __shfl_xor_sync(0xffffffffu, rm1, 2));

        float mn0 = fmaxf(m0, rm0), mn1 = fmaxf(m1, rm1);
        float al0 = __expf(m0 - mn0), al1 = __expf(m1 - mn1);
        m0 = mn0; m1 = mn1;

        float ls0 = 0.f, ls1 = 0.f;
        #pragma unroll
        for (int nf = 0; nf < 8; nf++) {
            sacc[nf][0] = __expf(sacc[nf][0] - m0);
            sacc[nf][1] = __expf(sacc[nf][1] - m0);
            sacc[nf][2] = __expf(sacc[nf][2] - m1);
            sacc[nf][3] = __expf(sacc[nf][3] - m1);
            ls0 += sacc[nf][0] + sacc[nf][1];
            ls1 += sacc[nf][2] + sacc[nf][3];
        }
        ls0 += __shfl_xor_sync(0xffffffffu, ls0, 1);
        ls0 += __shfl_xor_sync(0xffffffffu, ls0, 2);
        ls1 += __shfl_xor_sync(0xffffffffu, ls1, 1);
        ls1 += __shfl_xor_sync(0xffffffffu, ls1, 2);
        l0 = l0 * al0 + ls0;
        l1 = l1 * al1 + ls1;

        #pragma unroll
        for (int nf = 0; nf < 8; nf++) {
            oacc[nf][0] *= al0; oacc[nf][1] *= al0;
            oacc[nf][2] *= al1; oacc[nf][3] *= al1;
        }

        uint32_t pa[4][4];
        #pragma unroll
        for (int k2 = 0; k2 < 4; k2++) {
            pa[k2][0] = pack_h2(sacc[2*k2][0],   sacc[2*k2][1]);
            pa[k2][1] = pack_h2(sacc[2*k2][2],   sacc[2*k2][3]);
            pa[k2][2] = pack_h2(sacc[2*k2+1][0], sacc[2*k2+1][1]);
            pa[k2][3] = pack_h2(sacc[2*k2+1][2], sacc[2*k2+1][3]);
        }

        // ---- O += P V ----
        #pragma unroll
        for (int k2 = 0; k2 < 4; k2++) {
            uint32_t vrow = (uint32_t)(k2 * 16 + ((lane >> 3) & 1) * 8 + (lane & 7));
            uint32_t lhalf = (uint32_t)(((lane >> 4) & 1) * 16);
            #pragma unroll
            for (int np = 0; np < 4; np++) {
                uint32_t rh[4];
                ldsm_x4_t(rh, stgU + VOFF + vrow * AROW + np * 32 + lhalf);
                mma16816(oacc[2*np],   pa[k2], rh + 0);
                mma16816(oacc[2*np+1], pa[k2], rh + 2);
            }
        }
    }

    // ---- epilogue: O/l -> smem -> fp16 y (coalesced) ----
    __syncthreads();
    float* Osm = (float*)smem;
    const float inv0 = 1.f / l0, inv1 = 1.f / l1;
    #pragma unroll
    for (int nf = 0; nf < 8; nf++) {
        int c = nf * 8 + t * 2;
        Osm[(w * 16 + g)     * 72 + c]     = oacc[nf][0] * inv0;
        Osm[(w * 16 + g)     * 72 + c + 1] = oacc[nf][1] * inv0;
        Osm[(w * 16 + 8 + g) * 72 + c]     = oacc[nf][2] * inv1;
        Osm[(w * 16 + 8 + g) * 72 + c + 1] = oacc[nf][3] * inv1;
    }
    __syncthreads();

    {
        int r = tid >> 1, half = tid & 1;
        int b_ = bh >> 4, h = bh & 15;
        size_t base = ((size_t)b_ * Tt + q0 + r) * Cc + h * 64 + half * 32;
        uint16_t hb[32];
        #pragma unroll
        for (int i = 0; i < 32; i++)
            hb[i] = to_h(Osm[r * 72 + half * 32 + i]);
        #pragma unroll
        for (int c4 = 0; c4 < 4; c4++)
            *(uint4*)(g_yy + base + c4 * 8) = *(uint4*)(hb + c4 * 8);
    }
}

// ---------------------------------------------------------------------------
extern "C" void kernel_launch(void* const* d_in, const int* in_sizes, int n_in,
                              void* d_out, int out_size)
{
    const float* x      = (const float*)d_in[0];
    const float* W_attn = (const float*)d_in[1];
    const float* b_attn = (const float*)d_in[2];
    const float* W_proj = (const float*)d_in[3];
    const float* b_proj = (const float*)d_in[4];
    float* out = (float*)d_out;

    cudaFuncSetAttribute(mma_gemm_kernel<0>, cudaFuncAttributeMaxDynamicSharedMemorySize, GEMM_SMEM);
    cudaFuncSetAttribute(mma_gemm_kernel<1>, cudaFuncAttributeMaxDynamicSharedMemorySize, GEMM_SMEM);
    cudaFuncSetAttribute(attn_mma_kernel, cudaFuncAttributeMaxDynamicSharedMemorySize, ATT_SMEM);

    convert_kernel<<<2048, 256>>>(x);
    transpose_kernel<0, NQKV><<<dim3(NQKV / 32, Kdim / 32), dim3(32, 8)>>>(W_attn);
    transpose_kernel<1, Cc><<<dim3(Cc / 32, Kdim / 32), dim3(32, 8)>>>(W_proj);

    mma_gemm_kernel<0><<<dim3(NQKV / 128, Mrows / 128), 256, GEMM_SMEM>>>(b_attn, nullptr);

    attn_mma_kernel<<<dim3(Tt / 128, Bb * Hh), 256, ATT_SMEM>>>();

    mma_gemm_kernel<1><<<dim3(Cc / 128, Mrows / 128), 256, GEMM_SMEM>>>(b_proj, out);
}

// round 9
// speedup vs baseline: 9.5599x; 1.0314x over previous
#include <cuda_runtime.h>
#include <cuda_fp16.h>
#include <cstdint>

#define Bb 4
#define Tt 2048
#define Cc 1024
#define Hh 16
#define Dd 64
#define Kdim 1024
#define NQKV 3072
#define Mrows 8192

// ---------------------------------------------------------------------------
// scratch (__device__ globals; allocation-free). All fp16 (stored as u16).
// ---------------------------------------------------------------------------
__device__ uint16_t g_xx[(size_t)Mrows*Kdim];      // x fp16
__device__ uint16_t g_yy[(size_t)Mrows*Kdim];      // attention output fp16
__device__ uint16_t g_wta[(size_t)NQKV*Kdim];      // W_attn^T fp16
__device__ uint16_t g_wtp[(size_t)Cc*Kdim];        // W_proj^T fp16

// attention operands, [b,h,t,d] fp16 (q pre-scaled by 1/8)
__device__ uint16_t g_qq[(size_t)Bb*Hh*Tt*Dd];
__device__ uint16_t g_kk[(size_t)Bb*Hh*Tt*Dd];
__device__ uint16_t g_vv[(size_t)Bb*Hh*Tt*Dd];

// ---------------------------------------------------------------------------
// helpers
// ---------------------------------------------------------------------------
__device__ __forceinline__ uint32_t smem_u32(const void* p) {
    uint32_t a;
    asm("{ .reg .u64 t; cvta.to.shared.u64 t, %1; cvt.u32.u64 %0, t; }" : "=r"(a) : "l"(p));
    return a;
}
__device__ __forceinline__ void cp16(uint32_t dst, const void* src) {
    asm volatile("cp.async.cg.shared.global [%0], [%1], 16;" :: "r"(dst), "l"(src));
}
#define CP_COMMIT() asm volatile("cp.async.commit_group;" ::: "memory")
#define CP_WAIT(n)  asm volatile("cp.async.wait_group %0;" :: "n"(n) : "memory")

__device__ __forceinline__ void mma16816(float d[4], const uint32_t a[4], const uint32_t b[2]) {
    asm volatile(
        "mma.sync.aligned.m16n8k16.row.col.f32.f16.f16.f32 "
        "{%0,%1,%2,%3}, {%4,%5,%6,%7}, {%8,%9}, {%0,%1,%2,%3};"
        : "+f"(d[0]), "+f"(d[1]), "+f"(d[2]), "+f"(d[3])
        : "r"(a[0]), "r"(a[1]), "r"(a[2]), "r"(a[3]), "r"(b[0]), "r"(b[1]));
}
__device__ __forceinline__ void ldsm_x4(uint32_t r[4], uint32_t a) {
    asm volatile("ldmatrix.sync.aligned.m8n8.x4.shared.b16 {%0,%1,%2,%3}, [%4];"
        : "=r"(r[0]), "=r"(r[1]), "=r"(r[2]), "=r"(r[3]) : "r"(a));
}
__device__ __forceinline__ void ldsm_x4_t(uint32_t r[4], uint32_t a) {
    asm volatile("ldmatrix.sync.aligned.m8n8.x4.trans.shared.b16 {%0,%1,%2,%3}, [%4];"
        : "=r"(r[0]), "=r"(r[1]), "=r"(r[2]), "=r"(r[3]) : "r"(a));
}

__device__ __forceinline__ uint16_t to_h(float v) {
    __half hb = __float2half_rn(v);
    return *reinterpret_cast<uint16_t*>(&hb);
}
__device__ __forceinline__ uint32_t pack_h2(float a, float b) {
    __half2 h2 = __floats2half2_rn(a, b);
    return *reinterpret_cast<uint32_t*>(&h2);
}

// ---------------------------------------------------------------------------
// prep kernels
// ---------------------------------------------------------------------------
__global__ void convert_kernel(const float* __restrict__ src) {
    size_t n = (size_t)Mrows * Kdim;
    for (size_t i = (blockIdx.x * (size_t)blockDim.x + threadIdx.x) * 4; i < n;
         i += (size_t)gridDim.x * blockDim.x * 4) {
        float4 v = *(const float4*)(src + i);
        uint32_t p0 = pack_h2(v.x, v.y);
        uint32_t p1 = pack_h2(v.z, v.w);
        *(uint2*)&g_xx[i] = make_uint2(p0, p1);
    }
}

// transpose: W[Kdim][N] -> Wt[N][Kdim] fp16
template<int WHICH, int N>
__global__ void transpose_kernel(const float* __restrict__ W) {
    uint16_t* dst = (WHICH == 0) ? g_wta : g_wtp;
    __shared__ float t[32][33];
    int n0 = blockIdx.x * 32, k0 = blockIdx.y * 32;
    #pragma unroll
    for (int i = 0; i < 4; i++)
        t[threadIdx.y + 8 * i][threadIdx.x] = W[(size_t)(k0 + threadIdx.y + 8 * i) * N + n0 + threadIdx.x];
    __syncthreads();
    #pragma unroll
    for (int i = 0; i < 4; i++) {
        int n = n0 + threadIdx.y + 8 * i;
        int k = k0 + threadIdx.x;
        dst[(size_t)n * Kdim + k] = to_h(t[threadIdx.x][threadIdx.y + 8 * i]);
    }
}

// ---------------------------------------------------------------------------
// mma.sync fp16 GEMM (single pass), 128x128 block, BK=64, 8 warps (4Mx2N),
// 3-stage cp.async pipeline (1 barrier/stage), ldmatrix loads.
// ROWB=144 (=16*9): 16B-aligned rows; LDSM phase banks 4r mod 32 distinct.
// MODE 0: A=g_xx, B=W_attn^T -> scatter q/k/v fp16
// MODE 1: A=g_yy, B=W_proj^T -> fp32 out
// ---------------------------------------------------------------------------
#define BK 64
#define NSTG (Kdim / BK)           // 16
#define ROWB 144
#define MAT_B (128 * ROWB)         // 18432
#define STAGE_B (2 * MAT_B)        // 36864 (A, B)
#define GEMM_SMEM (3 * STAGE_B)    // 110592

__device__ __forceinline__ void preload_stage(uint32_t st,
        const uint16_t* __restrict__ As, const uint16_t* __restrict__ Bs,
        int row0, int col0, int kc, int tid)
{
    #pragma unroll
    for (int i = 0; i < 4; i++) {
        int idx = tid + i * 256;           // 0..1023
        int r = idx >> 3;                  // row 0..127
        int c = idx & 7;                   // 16B chunk 0..7
        uint32_t off = (uint32_t)(r * ROWB + c * 16);
        size_t gA = (size_t)(row0 + r) * Kdim + kc + c * 8;
        size_t gB = (size_t)(col0 + r) * Kdim + kc + c * 8;
        cp16(st + 0 * MAT_B + off, As + gA);
        cp16(st + 1 * MAT_B + off, Bs + gB);
    }
}

template<int MODE>
__global__ void __launch_bounds__(256, 2) mma_gemm_kernel(const float* __restrict__ bias,
                                                          float* __restrict__ out)
{
    extern __shared__ char smem[];
    const uint32_t sb = smem_u32(smem);
    const int tid  = threadIdx.x;
    const int wid  = tid >> 5;
    const int lane = tid & 31;
    const int g = lane >> 2;
    const int t = lane & 3;
    const int warpM = wid & 3;
    const int warpN = wid >> 2;
    const int row0 = blockIdx.y * 128;
    const int col0 = blockIdx.x * 128;

    const uint16_t* As = (MODE == 0) ? g_xx : g_yy;
    const uint16_t* Bs = (MODE == 0) ? g_wta : g_wtp;

    float acc[2][8][4];
    #pragma unroll
    for (int mt = 0; mt < 2; mt++)
        #pragma unroll
        for (int nt = 0; nt < 8; nt++)
            #pragma unroll
            for (int j = 0; j < 4; j++) acc[mt][nt][j] = 0.f;

    const uint32_t aRowIdx = (uint32_t)(((lane >> 3) & 1) * 8 + (lane & 7));
    const uint32_t aColOff = (uint32_t)(((lane >> 4) & 1) * 16);
    const uint32_t bRowIdx = (uint32_t)(((lane >> 4) & 1) * 8 + (lane & 7));
    const uint32_t bColOff = (uint32_t)(((lane >> 3) & 1) * 16);

    preload_stage(sb + 0 * STAGE_B, As, Bs, row0, col0, 0 * BK, tid); CP_COMMIT();
    preload_stage(sb + 1 * STAGE_B, As, Bs, row0, col0, 1 * BK, tid); CP_COMMIT();

    for (int s = 0; s < NSTG; s++) {
        if (s + 1 < NSTG) { CP_WAIT(1); } else { CP_WAIT(0); }
        __syncthreads();
        // preload s+2 into slot (s+2)%3 == (s-1)%3: all threads passed the
        // sync above, so compute(s-1) is complete and the slot is free.
        if (s + 2 < NSTG) {
            preload_stage(sb + (uint32_t)(((s + 2) % 3) * STAGE_B),
                          As, Bs, row0, col0, (s + 2) * BK, tid);
            CP_COMMIT();
        }

        const uint32_t stg = sb + (uint32_t)((s % 3) * STAGE_B);
        const uint32_t Am = stg + 0 * MAT_B;
        const uint32_t Bm = stg + 1 * MAT_B;

        #pragma unroll
        for (int ks = 0; ks < 4; ks++) {
            const uint32_t kByte = (uint32_t)(ks * 32);
            uint32_t ah[2][4];
            #pragma unroll
            for (int mt = 0; mt < 2; mt++) {
                uint32_t ra = (uint32_t)(warpM * 32 + mt * 16) + aRowIdx;
                ldsm_x4(ah[mt], Am + ra * ROWB + kByte + aColOff);
            }
            #pragma unroll
            for (int ntp = 0; ntp < 4; ntp++) {
                uint32_t rb = (uint32_t)(warpN * 64 + ntp * 16) + bRowIdx;
                uint32_t bb[4];
                ldsm_x4(bb, Bm + rb * ROWB + kByte + bColOff);
                #pragma unroll
                for (int half = 0; half < 2; half++)
                    #pragma unroll
                    for (int mt = 0; mt < 2; mt++)
                        mma16816(acc[mt][ntp * 2 + half], ah[mt], bb + half * 2);
            }
        }
    }

    #pragma unroll
    for (int mt = 0; mt < 2; mt++) {
        #pragma unroll
        for (int nt = 0; nt < 8; nt++) {
            #pragma unroll
            for (int half = 0; half < 2; half++) {
                int m = row0 + warpM * 32 + mt * 16 + g + half * 8;
                int n = col0 + warpN * 64 + nt * 8 + t * 2;
                float v0 = acc[mt][nt][half * 2 + 0] + bias[n];
                float v1 = acc[mt][nt][half * 2 + 1] + bias[n + 1];
                if (MODE == 0) {
                    int b_ = m >> 11;
                    int tt = m & 2047;
                    int which = n >> 10;
                    int cc = n & 1023;
                    int h = cc >> 6;
                    int d = cc & 63;
                    size_t base = (((size_t)b_ * Hh + h) * Tt + tt) * Dd + d;
                    if (which == 0) {
                        *(uint32_t*)&g_qq[base] = pack_h2(v0 * 0.125f, v1 * 0.125f);
                    } else if (which == 1) {
                        *(uint32_t*)&g_kk[base] = pack_h2(v0, v1);
                    } else {
                        *(uint32_t*)&g_vv[base] = pack_h2(v0, v1);
                    }
                } else {
                    float* p = out + (size_t)m * Cc + n;
                    p[0] = v0; p[1] = v1;
                }
            }
        }
    }
}

// ---------------------------------------------------------------------------
// Flash attention via mma.sync fp16, lazy guarded max.
// grid (Tt/128, Bb*Hh), 256 threads = 8 warps, warp = 16 q-rows x all keys.
// K-tile = 64 keys; stage = K + V. AROW=144.
// Offset M fixed after tile 0; rescale O only if a tile max exceeds M+8
// (warp vote; P <= e^8 = 2981 < fp16 max; sum <= 6.1e6 in fp32).
// ---------------------------------------------------------------------------
#define TK 64
#define NTILE (Tt / TK)             // 32
#define AROW 144
#define VOFF (64 * AROW)
#define STG_B (128 * AROW)          // 18432
#define ATT_SMEM (2 * STG_B)        // 36864

__global__ void __launch_bounds__(256, 2) attn_mma_kernel()
{
    extern __shared__ char smem[];
    const uint32_t sb = smem_u32(smem);
    const int tid  = threadIdx.x;
    const int w    = tid >> 5;
    const int lane = tid & 31;
    const int g = lane >> 2;
    const int t = lane & 3;
    const int q0 = blockIdx.x * 128;
    const int bh = blockIdx.y;

    const size_t seqBase = (size_t)bh * Tt * Dd;

    const uint32_t aRowIdx = (uint32_t)(((lane >> 3) & 1) * 8 + (lane & 7));
    const uint32_t aColOff = (uint32_t)(((lane >> 4) & 1) * 16);
    const uint32_t bRowIdx = (uint32_t)(((lane >> 4) & 1) * 8 + (lane & 7));
    const uint32_t bColOff = (uint32_t)(((lane >> 3) & 1) * 16);

    // ---- prologue: Q tile -> smem -> fragments ----
    #pragma unroll
    for (int j = 0; j < 4; j++) {
        int idx = tid + j * 256;
        int r = idx >> 3, c = idx & 7;
        size_t gsrc = seqBase + (size_t)(q0 + r) * Dd + c * 8;
        *(uint4*)(smem + r * AROW + c * 16) = *(const uint4*)(g_qq + gsrc);
    }
    __syncthreads();

    uint32_t qh[4][4];
    {
        uint32_t qrow = (uint32_t)(w * 16) + aRowIdx;
        #pragma unroll
        for (int kf = 0; kf < 4; kf++)
            ldsm_x4(qh[kf], sb + qrow * AROW + kf * 32 + aColOff);
    }
    __syncthreads();

    float oacc[8][4];
    #pragma unroll
    for (int nf = 0; nf < 8; nf++)
        #pragma unroll
        for (int j = 0; j < 4; j++) oacc[nf][j] = 0.f;
    float m0 = 0.f, m1 = 0.f, l0 = 0.f, l1 = 0.f;

    // stage 0
    #pragma unroll
    for (int j = 0; j < 2; j++) {
        int idx = tid + j * 256;
        int r = idx >> 3, c = idx & 7;
        uint32_t off = (uint32_t)(r * AROW + c * 16);
        size_t gsrc = seqBase + (size_t)r * Dd + c * 8;
        cp16(sb + off,        g_kk + gsrc);
        cp16(sb + VOFF + off, g_vv + gsrc);
    }
    CP_COMMIT();

    for (int kt = 0; kt < NTILE; kt++) {
        CP_WAIT(0);
        __syncthreads();
        if (kt + 1 < NTILE) {
            uint32_t st = sb + ((kt + 1) & 1) * STG_B;
            #pragma unroll
            for (int j = 0; j < 2; j++) {
                int idx = tid + j * 256;
                int r = idx >> 3, c = idx & 7;
                uint32_t off = (uint32_t)(r * AROW + c * 16);
                size_t gsrc = seqBase + (size_t)((kt + 1) * TK + r) * Dd + c * 8;
                cp16(st + off,        g_kk + gsrc);
                cp16(st + VOFF + off, g_vv + gsrc);
            }
            CP_COMMIT();
        }

        const uint32_t stgU = sb + (kt & 1) * STG_B;

        // ---- S = Q K^T ----
        float sacc[8][4];
        #pragma unroll
        for (int nf = 0; nf < 8; nf++)
            #pragma unroll
            for (int j = 0; j < 4; j++) sacc[nf][j] = 0.f;

        #pragma unroll
        for (int kf = 0; kf < 4; kf++) {
            uint32_t bf[8][2];
            #pragma unroll
            for (int p = 0; p < 4; p++) {
                uint32_t r4[4];
                ldsm_x4(r4, stgU + ((uint32_t)(p * 16) + bRowIdx) * AROW + kf * 32 + bColOff);
                bf[2*p][0] = r4[0]; bf[2*p][1] = r4[1];
                bf[2*p+1][0] = r4[2]; bf[2*p+1][1] = r4[3];
            }
            #pragma unroll
            for (int nf = 0; nf < 8; nf++) mma16816(sacc[nf], qh[kf], bf[nf]);
        }

        // ---- lazy guarded max ----
        float rm0 = sacc[0][0], rm1 = sacc[0][2];
        #pragma unroll
        for (int nf = 0; nf < 8; nf++) {
            rm0 = fmaxf(rm0, fmaxf(sacc[nf][0], sacc[nf][1]));
            rm1 = fmaxf(rm1, fmaxf(sacc[nf][2], sacc[nf][3]));
        }
        rm0 = fmaxf(rm0, __shfl_xor_sync(0xffffffffu, rm0, 1));
        rm0 = fmaxf(rm0, __shfl_xor_sync(0xffffffffu, rm0, 2));
        rm1 = fmaxf(rm1, __shfl_xor_sync(0xffffffffu, rm1, 1));
        rm1 = fmaxf(rm1, __shfl_xor_sync(0xffffffffu, rm1, 2));

        if (kt == 0) {
            m0 = rm0; m1 = rm1;
        } else if (__any_sync(0xffffffffu, (rm0 > m0 + 8.f) || (rm1 > m1 + 8.f))) {
            float mn0 = fmaxf(m0, rm0), mn1 = fmaxf(m1, rm1);
            float al0 = __expf(m0 - mn0), al1 = __expf(m1 - mn1);
            m0 = mn0; m1 = mn1;
            l0 *= al0; l1 *= al1;
            #pragma unroll
            for (int nf = 0; nf < 8; nf++) {
                oacc[nf][0] *= al0; oacc[nf][1] *= al0;
                oacc[nf][2] *= al1; oacc[nf][3] *= al1;
            }
        }

        float ls0 = 0.f, ls1 = 0.f;
        #pragma unroll
        for (int nf = 0; nf < 8; nf++) {
            sacc[nf][0] = __expf(sacc[nf][0] - m0);
            sacc[nf][1] = __expf(sacc[nf][1] - m0);
            sacc[nf][2] = __expf(sacc[nf][2] - m1);
            sacc[nf][3] = __expf(sacc[nf][3] - m1);
            ls0 += sacc[nf][0] + sacc[nf][1];
            ls1 += sacc[nf][2] + sacc[nf][3];
        }
        ls0 += __shfl_xor_sync(0xffffffffu, ls0, 1);
        ls0 += __shfl_xor_sync(0xffffffffu, ls0, 2);
        ls1 += __shfl_xor_sync(0xffffffffu, ls1, 1);
        ls1 += __shfl_xor_sync(0xffffffffu, ls1, 2);
        l0 += ls0;
        l1 += ls1;

        uint32_t pa[4][4];
        #pragma unroll
        for (int k2 = 0; k2 < 4; k2++) {
            pa[k2][0] = pack_h2(sacc[2*k2][0],   sacc[2*k2][1]);
            pa[k2][1] = pack_h2(sacc[2*k2][2],   sacc[2*k2][3]);
            pa[k2][2] = pack_h2(sacc[2*k2+1][0], sacc[2*k2+1][1]);
            pa[k2][3] = pack_h2(sacc[2*k2+1][2], sacc[2*k2+1][3]);
        }

        // ---- O += P V ----
        #pragma unroll
        for (int k2 = 0; k2 < 4; k2++) {
            uint32_t vrow = (uint32_t)(k2 * 16 + ((lane >> 3) & 1) * 8 + (lane & 7));
            uint32_t lhalf = (uint32_t)(((lane >> 4) & 1) * 16);
            #pragma unroll
            for (int np = 0; np < 4; np++) {
                uint32_t rh[4];
                ldsm_x4_t(rh, stgU + VOFF + vrow * AROW + np * 32 + lhalf);
                mma16816(oacc[2*np],   pa[k2], rh + 0);
                mma16816(oacc[2*np+1], pa[k2], rh + 2);
            }
        }
    }

    // ---- epilogue: O/l -> smem -> fp16 y (coalesced) ----
    __syncthreads();
    float* Osm = (float*)smem;
    const float inv0 = 1.f / l0, inv1 = 1.f / l1;
    #pragma unroll
    for (int nf = 0; nf < 8; nf++) {
        int c = nf * 8 + t * 2;
        Osm[(w * 16 + g)     * 72 + c]     = oacc[nf][0] * inv0;
        Osm[(w * 16 + g)     * 72 + c + 1] = oacc[nf][1] * inv0;
        Osm[(w * 16 + 8 + g) * 72 + c]     = oacc[nf][2] * inv1;
        Osm[(w * 16 + 8 + g) * 72 + c + 1] = oacc[nf][3] * inv1;
    }
    __syncthreads();

    {
        int r = tid >> 1, half = tid & 1;
        int b_ = bh >> 4, h = bh & 15;
        size_t base = ((size_t)b_ * Tt + q0 + r) * Cc + h * 64 + half * 32;
        uint16_t hb[32];
        #pragma unroll
        for (int i = 0; i < 32; i++)
            hb[i] = to_h(Osm[r * 72 + half * 32 + i]);
        #pragma unroll
        for (int c4 = 0; c4 < 4; c4++)
            *(uint4*)(g_yy + base + c4 * 8) = *(uint4*)(hb + c4 * 8);
    }
}

// ---------------------------------------------------------------------------
extern "C" void kernel_launch(void* const* d_in, const int* in_sizes, int n_in,
                              void* d_out, int out_size)
{
    const float* x      = (const float*)d_in[0];
    const float* W_attn = (const float*)d_in[1];
    const float* b_attn = (const float*)d_in[2];
    const float* W_proj = (const float*)d_in[3];
    const float* b_proj = (const float*)d_in[4];
    float* out = (float*)d_out;

    cudaFuncSetAttribute(mma_gemm_kernel<0>, cudaFuncAttributeMaxDynamicSharedMemorySize, GEMM_SMEM);
    cudaFuncSetAttribute(mma_gemm_kernel<1>, cudaFuncAttributeMaxDynamicSharedMemorySize, GEMM_SMEM);
    cudaFuncSetAttribute(attn_mma_kernel, cudaFuncAttributeMaxDynamicSharedMemorySize, ATT_SMEM);

    convert_kernel<<<2048, 256>>>(x);
    transpose_kernel<0, NQKV><<<dim3(NQKV / 32, Kdim / 32), dim3(32, 8)>>>(W_attn);
    transpose_kernel<1, Cc><<<dim3(Cc / 32, Kdim / 32), dim3(32, 8)>>>(W_proj);

    mma_gemm_kernel<0><<<dim3(NQKV / 128, Mrows / 128), 256, GEMM_SMEM>>>(b_attn, nullptr);

    attn_mma_kernel<<<dim3(Tt / 128, Bb * Hh), 256, ATT_SMEM>>>();

    mma_gemm_kernel<1><<<dim3(Cc / 128, Mrows / 128), 256, GEMM_SMEM>>>(b_proj, out);
}